// round 4
// baseline (speedup 1.0000x reference)
#include <cuda_runtime.h>
#include <math.h>

#define NN 30000
#define EE 510000      // 30000*16 + 30000 self loops
#define TT 2
#define KDIM 128       // F_IN == H1 == 128 (GEMM K for both layers)

// ---------------- scratch (device globals; no allocation allowed) ----------------
__device__ float  g_h[(size_t)NN * 256];     // GEMM output, max 2C = 256
__device__ float  g_mu0[(size_t)NN * 128];   // layer outputs / fused inputs
__device__ float  g_mu1[(size_t)NN * 128];
__device__ float  g_si[NN];
__device__ float  g_sj[NN];
__device__ float  g_invdeg[TT][NN];
__device__ int    g_deg[TT][NN];
__device__ int    g_rowptr[TT][NN + 1];
__device__ int    g_woff[TT][NN];
__device__ int    g_csrc[TT][EE];
__device__ double g_acc[8];  // [0..3] ixz sums (L1t0,L1t1,L2t0,L2t1), [4..7] skl sums

// ---------------- helpers ----------------
__device__ __forceinline__ float blockReduceSum(float v, float* sm) {
    int lane = threadIdx.x & 31, wid = threadIdx.x >> 5;
#pragma unroll
    for (int o = 16; o; o >>= 1) v += __shfl_down_sync(0xffffffffu, v, o);
    if (lane == 0) sm[wid] = v;
    __syncthreads();
    int nw = (blockDim.x + 31) >> 5;
    v = (threadIdx.x < nw) ? sm[threadIdx.x] : 0.f;
    if (wid == 0) {
#pragma unroll
        for (int o = 16; o; o >>= 1) v += __shfl_down_sync(0xffffffffu, v, o);
    }
    return v;  // valid on thread 0
}

// ---------------- setup kernels ----------------
__global__ void zero_kernel() {
    int i = blockIdx.x * blockDim.x + threadIdx.x;
    if (i < TT * NN) (&g_deg[0][0])[i] = 0;
    if (i < 8) g_acc[i] = 0.0;
}

__global__ void hist_kernel(const int* __restrict__ dst, int t) {
    int e = blockIdx.x * blockDim.x + threadIdx.x;
    if (e < EE) atomicAdd(&g_deg[t][dst[e]], 1);
}

__global__ void scan_kernel(int t) {
    const int T = 1024;
    int tid = threadIdx.x;
    const int chunk = (NN + T - 1) / T;  // 30
    int s0 = tid * chunk;
    int sum = 0;
    for (int i = 0; i < chunk; i++) {
        int idx = s0 + i;
        if (idx < NN) sum += g_deg[t][idx];
    }
    int lane = tid & 31, wid = tid >> 5;
    int v = sum;
#pragma unroll
    for (int o = 1; o < 32; o <<= 1) {
        int u = __shfl_up_sync(0xffffffffu, v, o);
        if (lane >= o) v += u;
    }
    __shared__ int ws[32];
    if (lane == 31) ws[wid] = v;
    __syncthreads();
    if (wid == 0) {
        int w = ws[lane];
#pragma unroll
        for (int o = 1; o < 32; o <<= 1) {
            int u = __shfl_up_sync(0xffffffffu, w, o);
            if (lane >= o) w += u;
        }
        ws[lane] = w;
    }
    __syncthreads();
    int excl = (v - sum) + (wid > 0 ? ws[wid - 1] : 0);
    int run = excl;
    for (int i = 0; i < chunk; i++) {
        int idx = s0 + i;
        if (idx < NN) {
            int d = g_deg[t][idx];
            g_rowptr[t][idx] = run;
            g_woff[t][idx] = run;
            g_invdeg[t][idx] = 1.0f / (float)d;
            run += d;
        }
    }
    if (tid == T - 1) g_rowptr[t][NN] = run;
}

__global__ void scatter_kernel(const int* __restrict__ src, const int* __restrict__ dst, int t) {
    int e = blockIdx.x * blockDim.x + threadIdx.x;
    if (e < EE) {
        int d = dst[e];
        int pos = atomicAdd(&g_woff[t][d], 1);
        g_csrc[t][pos] = src[e];
    }
}

// ---------------- GEMM: C[M, Ncols] = A[M,128] * B[128, Ncols] ----------------
// 128x128 tile per block, 256 threads, 8x8 per thread, BK=8, global prefetch.
__global__ void __launch_bounds__(256, 2)
gemm_kernel(const float* __restrict__ A, const float* __restrict__ B,
            float* __restrict__ C, int M, int Ncols) {
    __shared__ float As[8][128];
    __shared__ float Bs[8][128];
    int tid = threadIdx.x;
    int tx = tid & 15;        // 0..15 -> col group
    int ty = tid >> 4;        // 0..15 -> row group
    int row0 = blockIdx.y * 128;
    int col0 = blockIdx.x * 128;
    int a_row = tid >> 1;           // 0..127
    int a_k   = (tid & 1) * 4;      // 0 or 4
    int b_k   = tid >> 5;           // 0..7
    int b_n   = (tid & 31) * 4;
    bool a_ok = (row0 + a_row) < M;
    const float* Aptr = A + (size_t)(row0 + a_row) * KDIM + a_k;
    const float* Bptr = B + (size_t)b_k * Ncols + col0 + b_n;

    float acc[8][8] = {};
    float4 av = a_ok ? *(const float4*)Aptr : make_float4(0.f, 0.f, 0.f, 0.f);
    float4 bv = *(const float4*)Bptr;

    for (int k0 = 0; k0 < KDIM; k0 += 8) {
        As[a_k + 0][a_row] = av.x;
        As[a_k + 1][a_row] = av.y;
        As[a_k + 2][a_row] = av.z;
        As[a_k + 3][a_row] = av.w;
        *(float4*)&Bs[b_k][b_n] = bv;
        __syncthreads();
        if (k0 + 8 < KDIM) {
            if (a_ok) av = *(const float4*)(Aptr + k0 + 8);
            bv = *(const float4*)(Bptr + (size_t)(k0 + 8) * Ncols);
        }
#pragma unroll
        for (int k = 0; k < 8; k++) {
            float a[8], b[8];
            *(float4*)&a[0] = *(const float4*)&As[k][ty * 8];
            *(float4*)&a[4] = *(const float4*)&As[k][ty * 8 + 4];
            *(float4*)&b[0] = *(const float4*)&Bs[k][tx * 8];
            *(float4*)&b[4] = *(const float4*)&Bs[k][tx * 8 + 4];
#pragma unroll
            for (int i = 0; i < 8; i++)
#pragma unroll
                for (int j = 0; j < 8; j++) acc[i][j] = fmaf(a[i], b[j], acc[i][j]);
        }
        __syncthreads();
    }
#pragma unroll
    for (int i = 0; i < 8; i++) {
        int r = row0 + ty * 8 + i;
        if (r < M) {
            *(float4*)&C[(size_t)r * Ncols + col0 + tx * 8] =
                make_float4(acc[i][0], acc[i][1], acc[i][2], acc[i][3]);
            *(float4*)&C[(size_t)r * Ncols + col0 + tx * 8 + 4] =
                make_float4(acc[i][4], acc[i][5], acc[i][6], acc[i][7]);
        }
    }
}

// ---------------- per-node attention scores ----------------
__global__ void scores_kernel(const float* __restrict__ h, const float* __restrict__ att, int TC) {
    int gw = (blockIdx.x * blockDim.x + threadIdx.x) >> 5;
    int lane = threadIdx.x & 31;
    if (gw >= NN) return;
    const float* row = h + (size_t)gw * TC;
    float a = 0.f, b = 0.f;
    for (int i = lane; i < TC; i += 32) {
        float v = row[i];
        a = fmaf(v, att[i], a);
        b = fmaf(v, att[TC + i], b);
    }
#pragma unroll
    for (int o = 16; o; o >>= 1) {
        a += __shfl_down_sync(0xffffffffu, a, o);
        b += __shfl_down_sync(0xffffffffu, b, o);
    }
    if (lane == 0) {
        g_si[gw] = a;
        g_sj[gw] = b;
    }
}

// ---------------- aggregation (alpha + skl fused) + KL epilogue ----------------
template <int C>
__global__ void agg_kernel(const float4* __restrict__ h4, const int* __restrict__ csrc,
                           const int* __restrict__ rowptr, const float* __restrict__ si,
                           const float* __restrict__ sj, const float* __restrict__ invdeg,
                           const float* __restrict__ bias, float* __restrict__ mu_out,
                           double* __restrict__ ixz_slot, double* __restrict__ skl_slot) {
    constexpr int NT = C / 2;  // threads per block == float4s per TC-row
    __shared__ float s_alpha[NT];
    __shared__ int s_src[NT];
    __shared__ float s_std[C];
    __shared__ float s_red[32];
    int n = blockIdx.x, tid = threadIdx.x;
    int start = rowptr[n], end = rowptr[n + 1];
    float si_n = si[n], inv = invdeg[n];
    const float q = 1.f / (1.f + expf(-1.f / 15.f));
    const float lq = logf(q), l1q = logf(1.f - q);
    float4 acc = make_float4(0.f, 0.f, 0.f, 0.f);
    float skl_loc = 0.f;
    for (int base = start; base < end; base += NT) {
        int cnt = min(NT, end - base);
        if (tid < cnt) {
            int s = csrc[base + tid];
            float l = si_n + sj[s];
            l = l > 0.f ? l : 0.2f * l;
            float p = 1.f / (1.f + expf(-l));
            p = fminf(fmaxf(p, 0.01f), 0.99f);
            s_alpha[tid] = p * inv;
            s_src[tid] = s;
            skl_loc += p * (logf(p) - lq) + (1.f - p) * (logf(1.f - p) - l1q);
        }
        __syncthreads();
        for (int i = 0; i < cnt; i++) {
            float a = s_alpha[i];
            float4 v = h4[(size_t)s_src[i] * NT + tid];
            acc.x = fmaf(a, v.x, acc.x);
            acc.y = fmaf(a, v.y, acc.y);
            acc.z = fmaf(a, v.z, acc.z);
            acc.w = fmaf(a, v.w, acc.w);
        }
        __syncthreads();
    }
    float4 bv = *(const float4*)&bias[tid * 4];
    acc.x += bv.x; acc.y += bv.y; acc.z += bv.z; acc.w += bv.w;
    if (tid >= NT / 2) {
        float xs[4] = {acc.x, acc.y, acc.z, acc.w};
        float* sp = &s_std[tid * 4 - C];
#pragma unroll
        for (int j = 0; j < 4; j++)
            sp[j] = fmaxf(xs[j], 0.f) + log1pf(expf(-fabsf(xs[j]))) + 1e-10f;
    }
    __syncthreads();
    float kl = 0.f;
    if (tid < NT / 2) {
        float mus[4] = {acc.x, acc.y, acc.z, acc.w};
#pragma unroll
        for (int j = 0; j < 4; j++) {
            float sd = s_std[tid * 4 + j];
            kl += -logf(sd) + 0.5f * fmaf(sd, sd, mus[j] * mus[j]) - 0.5f;
        }
        ((float4*)mu_out)[(size_t)n * (NT / 2) + tid] = acc;
    }
    float t1 = blockReduceSum(kl, s_red);
    if (tid == 0) atomicAdd(ixz_slot, (double)t1);
    __syncthreads();
    float t2 = blockReduceSum(skl_loc, s_red);
    if (tid == 0) atomicAdd(skl_slot, (double)t2);
}

// ---------------- temporal fusion / activations ----------------
__global__ void fuse1_kernel() {
    int i = blockIdx.x * blockDim.x + threadIdx.x;
    if (i < NN * 128) {
        float m0 = g_mu0[i], m1 = g_mu1[i];
        g_mu1[i] = fmaxf(0.4f * m0 + 0.2f * m1, 0.f);  // h1[1] = relu(0.4*mu0 + 0.2*mu1)
        g_mu0[i] = fmaxf(m0, 0.f);                      // h1[0] = relu(mu0)
    }
}

__global__ void fuse2_kernel(float* __restrict__ out) {
    int i = blockIdx.x * blockDim.x + threadIdx.x;
    if (i < NN * 64) out[NN * 64 + i] = 0.4f * out[i] + 0.2f * g_mu1[i];
}

__global__ void finalize_kernel(float* __restrict__ out, int out_size) {
    double ixz = (g_acc[0] + g_acc[1] + g_acc[2] + g_acc[3]) / (4.0 * (double)NN);
    double skl = (g_acc[4] + g_acc[5] + g_acc[6] + g_acc[7]) / (4.0 * (double)EE);
    out[out_size - 2] = (float)ixz;
    out[out_size - 1] = (float)skl;
}

// ---------------- launch ----------------
extern "C" void kernel_launch(void* const* d_in, const int* in_sizes, int n_in,
                              void* d_out, int out_size) {
    const float* x_all = (const float*)d_in[0];   // [T, N, 128]
    const int* ei = (const int*)d_in[1];          // [T, 2, E]
    const float* W1 = (const float*)d_in[2];      // [128, 256]
    const float* att1 = (const float*)d_in[3];    // [512]
    const float* b1 = (const float*)d_in[4];      // [256]
    const float* W2 = (const float*)d_in[5];      // [128, 128]
    const float* att2 = (const float*)d_in[6];    // [256]
    const float* b2 = (const float*)d_in[7];      // [128]
    float* out = (float*)d_out;

    float *p_h, *p_mu0, *p_mu1, *p_si, *p_sj, *p_invdeg;
    int *p_csrc, *p_rowptr;
    double* p_acc;
    cudaGetSymbolAddress((void**)&p_h, g_h);
    cudaGetSymbolAddress((void**)&p_mu0, g_mu0);
    cudaGetSymbolAddress((void**)&p_mu1, g_mu1);
    cudaGetSymbolAddress((void**)&p_si, g_si);
    cudaGetSymbolAddress((void**)&p_sj, g_sj);
    cudaGetSymbolAddress((void**)&p_invdeg, g_invdeg);
    cudaGetSymbolAddress((void**)&p_csrc, g_csrc);
    cudaGetSymbolAddress((void**)&p_rowptr, g_rowptr);
    cudaGetSymbolAddress((void**)&p_acc, g_acc);

    const int EB = (EE + 255) / 256;

    zero_kernel<<<(TT * NN + 255) / 256, 256>>>();
    for (int t = 0; t < TT; t++) {
        const int* src = ei + (size_t)t * 2 * EE;
        const int* dst = src + EE;
        hist_kernel<<<EB, 256>>>(dst, t);
        scan_kernel<<<1, 1024>>>(t);
        scatter_kernel<<<EB, 256>>>(src, dst, t);
    }

    // -------- layer 1 (C = 128) --------
    for (int t = 0; t < TT; t++) {
        gemm_kernel<<<dim3(256 / 128, (NN + 127) / 128), 256>>>(
            x_all + (size_t)t * NN * KDIM, W1, p_h, NN, 256);
        scores_kernel<<<(NN * 32 + 255) / 256, 256>>>(p_h, att1, 256);
        agg_kernel<128><<<NN, 64>>>((const float4*)p_h, p_csrc + (size_t)t * EE,
                                    p_rowptr + (size_t)t * (NN + 1), p_si, p_sj,
                                    p_invdeg + (size_t)t * NN, b1,
                                    t ? p_mu1 : p_mu0, p_acc + t, p_acc + 4 + t);
    }
    fuse1_kernel<<<(NN * 128 + 255) / 256, 256>>>();

    // -------- layer 2 (C = 64) --------
    for (int t = 0; t < TT; t++) {
        const float* xin = t ? p_mu1 : p_mu0;
        gemm_kernel<<<dim3(128 / 128, (NN + 127) / 128), 256>>>(xin, W2, p_h, NN, 128);
        scores_kernel<<<(NN * 32 + 255) / 256, 256>>>(p_h, att2, 128);
        agg_kernel<64><<<NN, 32>>>((const float4*)p_h, p_csrc + (size_t)t * EE,
                                   p_rowptr + (size_t)t * (NN + 1), p_si, p_sj,
                                   p_invdeg + (size_t)t * NN, b2,
                                   t ? p_mu1 : out, p_acc + 2 + t, p_acc + 6 + t);
    }
    fuse2_kernel<<<(NN * 64 + 255) / 256, 256>>>(out);
    finalize_kernel<<<1, 1>>>(out, out_size);
}

// round 5
// speedup vs baseline: 1.1709x; 1.1709x over previous
#include <cuda_runtime.h>
#include <math.h>

#define NN 30000
#define EE 510000      // 30000*16 + 30000 self loops
#define TT 2
#define KDIM 128       // F_IN == H1 == 128 (GEMM K for both layers)

// ---------------- scratch (device globals; no allocation allowed) ----------------
__device__ float  g_h[(size_t)NN * 256];     // GEMM output, max 2C = 256
__device__ float  g_mu0[(size_t)NN * 128];   // layer outputs / fused inputs
__device__ float  g_mu1[(size_t)NN * 128];
__device__ float  g_si[NN];
__device__ float  g_sj[NN];
__device__ float  g_invdeg[TT][NN];
__device__ int    g_deg[TT][NN];
__device__ int    g_rowptr[TT][NN + 1];
__device__ int    g_woff[TT][NN];
__device__ int    g_csrc[TT][EE];
__device__ double g_acc[8];  // [0..3] ixz sums, [4..7] skl sums

// ---------------- helpers ----------------
__device__ __forceinline__ float blockReduceSum(float v, float* sm) {
    int lane = threadIdx.x & 31, wid = threadIdx.x >> 5;
#pragma unroll
    for (int o = 16; o; o >>= 1) v += __shfl_down_sync(0xffffffffu, v, o);
    if (lane == 0) sm[wid] = v;
    __syncthreads();
    int nw = (blockDim.x + 31) >> 5;
    v = (threadIdx.x < nw) ? sm[threadIdx.x] : 0.f;
    if (wid == 0) {
#pragma unroll
        for (int o = 16; o; o >>= 1) v += __shfl_down_sync(0xffffffffu, v, o);
    }
    return v;  // valid on thread 0
}

// ---------------- setup kernels ----------------
__global__ void zero_kernel() {
    int i = blockIdx.x * blockDim.x + threadIdx.x;
    if (i < TT * NN) (&g_deg[0][0])[i] = 0;
    if (i < 8) g_acc[i] = 0.0;
}

__global__ void hist_kernel(const int* __restrict__ dst, int t) {
    int e = blockIdx.x * blockDim.x + threadIdx.x;
    if (e < EE) atomicAdd(&g_deg[t][dst[e]], 1);
}

__global__ void scan_kernel(int t) {
    const int T = 1024;
    int tid = threadIdx.x;
    const int chunk = (NN + T - 1) / T;  // 30
    int s0 = tid * chunk;
    int sum = 0;
    for (int i = 0; i < chunk; i++) {
        int idx = s0 + i;
        if (idx < NN) sum += g_deg[t][idx];
    }
    int lane = tid & 31, wid = tid >> 5;
    int v = sum;
#pragma unroll
    for (int o = 1; o < 32; o <<= 1) {
        int u = __shfl_up_sync(0xffffffffu, v, o);
        if (lane >= o) v += u;
    }
    __shared__ int ws[32];
    if (lane == 31) ws[wid] = v;
    __syncthreads();
    if (wid == 0) {
        int w = ws[lane];
#pragma unroll
        for (int o = 1; o < 32; o <<= 1) {
            int u = __shfl_up_sync(0xffffffffu, w, o);
            if (lane >= o) w += u;
        }
        ws[lane] = w;
    }
    __syncthreads();
    int excl = (v - sum) + (wid > 0 ? ws[wid - 1] : 0);
    int run = excl;
    for (int i = 0; i < chunk; i++) {
        int idx = s0 + i;
        if (idx < NN) {
            int d = g_deg[t][idx];
            g_rowptr[t][idx] = run;
            g_woff[t][idx] = run;
            g_invdeg[t][idx] = 1.0f / (float)d;
            run += d;
        }
    }
    if (tid == T - 1) g_rowptr[t][NN] = run;
}

__global__ void scatter_kernel(const int* __restrict__ src, const int* __restrict__ dst, int t) {
    int e = blockIdx.x * blockDim.x + threadIdx.x;
    if (e < EE) {
        int d = dst[e];
        int pos = atomicAdd(&g_woff[t][d], 1);
        g_csrc[t][pos] = src[e];
    }
}

// ---------------- GEMM: C[M, Ncols] = A[M,128] * B[128, Ncols] ----------------
// 128x64 tile per block, BK=16, 256 threads, 4x8 per thread.
// Per k-step per thread: 32 FFMA vs 3 LDS.128 -> ~91% FMA issue.
#define BM 128
#define BN 64
#define BK 16
__global__ void __launch_bounds__(256)
gemm_kernel(const float* __restrict__ A, const float* __restrict__ B,
            float* __restrict__ C, int M, int Ncols) {
    __shared__ float As[BK][BM];
    __shared__ float Bs[BK][BN];
    int tid = threadIdx.x;
    int tx = tid & 7;         // 0..7  -> col group of 8
    int ty = tid >> 3;        // 0..31 -> row group of 4
    int row0 = blockIdx.y * BM;
    int col0 = blockIdx.x * BN;
    int a_row = tid >> 1;         // 0..127
    int a_k   = (tid & 1) * 4;    // 0 or 4
    int b_k   = tid >> 4;         // 0..15
    int b_n   = (tid & 15) * 4;
    bool a_ok = (row0 + a_row) < M;
    const float* Aptr = A + (size_t)(row0 + a_row) * KDIM;
    const float* Bptr = B + (size_t)b_k * Ncols + col0 + b_n;

    float acc[4][8] = {};
    float4 z4 = make_float4(0.f, 0.f, 0.f, 0.f);
    float4 av0 = a_ok ? *(const float4*)(Aptr + a_k) : z4;
    float4 av1 = a_ok ? *(const float4*)(Aptr + a_k + 8) : z4;
    float4 bv = *(const float4*)Bptr;

    for (int k0 = 0; k0 < KDIM; k0 += BK) {
        As[a_k + 0][a_row] = av0.x;
        As[a_k + 1][a_row] = av0.y;
        As[a_k + 2][a_row] = av0.z;
        As[a_k + 3][a_row] = av0.w;
        As[a_k + 8][a_row] = av1.x;
        As[a_k + 9][a_row] = av1.y;
        As[a_k + 10][a_row] = av1.z;
        As[a_k + 11][a_row] = av1.w;
        *(float4*)&Bs[b_k][b_n] = bv;
        __syncthreads();
        if (k0 + BK < KDIM) {
            if (a_ok) {
                av0 = *(const float4*)(Aptr + k0 + BK + a_k);
                av1 = *(const float4*)(Aptr + k0 + BK + a_k + 8);
            }
            bv = *(const float4*)(Bptr + (size_t)(k0 + BK) * Ncols);
        }
#pragma unroll
        for (int k = 0; k < BK; k++) {
            float a[4], b[8];
            *(float4*)&a[0] = *(const float4*)&As[k][ty * 4];
            *(float4*)&b[0] = *(const float4*)&Bs[k][tx * 8];
            *(float4*)&b[4] = *(const float4*)&Bs[k][tx * 8 + 4];
#pragma unroll
            for (int i = 0; i < 4; i++)
#pragma unroll
                for (int j = 0; j < 8; j++) acc[i][j] = fmaf(a[i], b[j], acc[i][j]);
        }
        __syncthreads();
    }
#pragma unroll
    for (int i = 0; i < 4; i++) {
        int r = row0 + ty * 4 + i;
        if (r < M) {
            *(float4*)&C[(size_t)r * Ncols + col0 + tx * 8] =
                make_float4(acc[i][0], acc[i][1], acc[i][2], acc[i][3]);
            *(float4*)&C[(size_t)r * Ncols + col0 + tx * 8 + 4] =
                make_float4(acc[i][4], acc[i][5], acc[i][6], acc[i][7]);
        }
    }
}

// ---------------- per-node attention scores ----------------
__global__ void scores_kernel(const float4* __restrict__ h4, const float* __restrict__ att, int TC) {
    int gw = (blockIdx.x * blockDim.x + threadIdx.x) >> 5;
    int lane = threadIdx.x & 31;
    if (gw >= NN) return;
    int n4 = TC >> 2;
    const float4* row = h4 + (size_t)gw * n4;
    float a = 0.f, b = 0.f;
    for (int i = lane; i < n4; i += 32) {
        float4 v = row[i];
        a = fmaf(v.x, att[i * 4 + 0], a);
        a = fmaf(v.y, att[i * 4 + 1], a);
        a = fmaf(v.z, att[i * 4 + 2], a);
        a = fmaf(v.w, att[i * 4 + 3], a);
        b = fmaf(v.x, att[TC + i * 4 + 0], b);
        b = fmaf(v.y, att[TC + i * 4 + 1], b);
        b = fmaf(v.z, att[TC + i * 4 + 2], b);
        b = fmaf(v.w, att[TC + i * 4 + 3], b);
    }
#pragma unroll
    for (int o = 16; o; o >>= 1) {
        a += __shfl_down_sync(0xffffffffu, a, o);
        b += __shfl_down_sync(0xffffffffu, b, o);
    }
    if (lane == 0) {
        g_si[gw] = a;
        g_sj[gw] = b;
    }
}

// ---------------- aggregation (alpha + skl fused) + KL epilogue ----------------
// One block per node, one thread per output channel (2C threads) — round-1 shape.
template <int C>
__global__ void agg_kernel(const float* __restrict__ h, const int* __restrict__ csrc,
                           const int* __restrict__ rowptr, const float* __restrict__ si,
                           const float* __restrict__ sj, const float* __restrict__ invdeg,
                           const float* __restrict__ bias, float* __restrict__ mu_out,
                           double* __restrict__ ixz_slot, double* __restrict__ skl_slot) {
    constexpr int TC = 2 * C;
    __shared__ float s_alpha[TC];
    __shared__ int s_src[TC];
    __shared__ float s_std[C];
    __shared__ float s_red[32];
    int n = blockIdx.x, tid = threadIdx.x;
    int start = rowptr[n], end = rowptr[n + 1];
    float si_n = si[n], inv = invdeg[n];
    const float q = 1.f / (1.f + expf(-1.f / 15.f));
    const float lq = logf(q), l1q = logf(1.f - q);
    float acc = 0.f, skl_loc = 0.f;
    for (int base = start; base < end; base += TC) {
        int cnt = min(TC, end - base);
        if (tid < cnt) {
            int s = csrc[base + tid];
            float l = si_n + sj[s];
            l = l > 0.f ? l : 0.2f * l;
            float p = 1.f / (1.f + expf(-l));
            p = fminf(fmaxf(p, 0.01f), 0.99f);
            s_alpha[tid] = p * inv;
            s_src[tid] = s;
            skl_loc += p * (logf(p) - lq) + (1.f - p) * (logf(1.f - p) - l1q);
        }
        __syncthreads();
        for (int i = 0; i < cnt; i++)
            acc = fmaf(s_alpha[i], h[(size_t)s_src[i] * TC + tid], acc);
        __syncthreads();
    }
    acc += bias[tid];
    if (tid >= C) {
        float x = acc;
        s_std[tid - C] = fmaxf(x, 0.f) + log1pf(expf(-fabsf(x))) + 1e-10f;
    }
    __syncthreads();
    float kl = 0.f;
    if (tid < C) {
        float mu = acc, sd = s_std[tid];
        kl = -logf(sd) + 0.5f * fmaf(sd, sd, mu * mu) - 0.5f;
        mu_out[(size_t)n * C + tid] = mu;
    }
    float t1 = blockReduceSum(kl, s_red);
    if (tid == 0) atomicAdd(ixz_slot, (double)t1);
    __syncthreads();
    float t2 = blockReduceSum(skl_loc, s_red);
    if (tid == 0) atomicAdd(skl_slot, (double)t2);
}

// ---------------- temporal fusion / activations ----------------
__global__ void fuse1_kernel() {
    int i = blockIdx.x * blockDim.x + threadIdx.x;
    if (i < NN * 128) {
        float m0 = g_mu0[i], m1 = g_mu1[i];
        g_mu1[i] = fmaxf(0.4f * m0 + 0.2f * m1, 0.f);  // h1[1] = relu(0.4*mu0 + 0.2*mu1)
        g_mu0[i] = fmaxf(m0, 0.f);                      // h1[0] = relu(mu0)
    }
}

__global__ void fuse2_kernel(float* __restrict__ out) {
    int i = blockIdx.x * blockDim.x + threadIdx.x;
    if (i < NN * 64) out[NN * 64 + i] = 0.4f * out[i] + 0.2f * g_mu1[i];
}

__global__ void finalize_kernel(float* __restrict__ out, int out_size) {
    double ixz = (g_acc[0] + g_acc[1] + g_acc[2] + g_acc[3]) / (4.0 * (double)NN);
    double skl = (g_acc[4] + g_acc[5] + g_acc[6] + g_acc[7]) / (4.0 * (double)EE);
    out[out_size - 2] = (float)ixz;
    out[out_size - 1] = (float)skl;
}

// ---------------- launch ----------------
extern "C" void kernel_launch(void* const* d_in, const int* in_sizes, int n_in,
                              void* d_out, int out_size) {
    const float* x_all = (const float*)d_in[0];   // [T, N, 128]
    const int* ei = (const int*)d_in[1];          // [T, 2, E]
    const float* W1 = (const float*)d_in[2];      // [128, 256]
    const float* att1 = (const float*)d_in[3];    // [512]
    const float* b1 = (const float*)d_in[4];      // [256]
    const float* W2 = (const float*)d_in[5];      // [128, 128]
    const float* att2 = (const float*)d_in[6];    // [256]
    const float* b2 = (const float*)d_in[7];      // [128]
    float* out = (float*)d_out;

    float *p_h, *p_mu0, *p_mu1, *p_si, *p_sj, *p_invdeg;
    int *p_csrc, *p_rowptr;
    double* p_acc;
    cudaGetSymbolAddress((void**)&p_h, g_h);
    cudaGetSymbolAddress((void**)&p_mu0, g_mu0);
    cudaGetSymbolAddress((void**)&p_mu1, g_mu1);
    cudaGetSymbolAddress((void**)&p_si, g_si);
    cudaGetSymbolAddress((void**)&p_sj, g_sj);
    cudaGetSymbolAddress((void**)&p_invdeg, g_invdeg);
    cudaGetSymbolAddress((void**)&p_csrc, g_csrc);
    cudaGetSymbolAddress((void**)&p_rowptr, g_rowptr);
    cudaGetSymbolAddress((void**)&p_acc, g_acc);

    const int EB = (EE + 255) / 256;
    const int* src0 = ei;
    const int* dst0 = ei + EE;
    const int* src1 = ei + (size_t)2 * EE;
    const int* dst1 = ei + (size_t)3 * EE;

    // Launch order puts a layer-1 GEMM where ncu's bounded capture lands,
    // so the next profile shows the dominant kernel instead of scatter.
    zero_kernel<<<(TT * NN + 255) / 256, 256>>>();                       // 0
    hist_kernel<<<EB, 256>>>(dst0, 0);                                   // 1
    scan_kernel<<<1, 1024>>>(0);                                         // 2
    scatter_kernel<<<EB, 256>>>(src0, dst0, 0);                          // 3
    hist_kernel<<<EB, 256>>>(dst1, 1);                                   // 4
    scan_kernel<<<1, 1024>>>(1);                                         // 5
    gemm_kernel<<<dim3(256 / BN, (NN + BM - 1) / BM), 256>>>(            // 6 <- profiled
        x_all, W1, p_h, NN, 256);
    scatter_kernel<<<EB, 256>>>(src1, dst1, 1);                          // 7

    // -------- layer 1, t = 0 --------
    scores_kernel<<<(NN * 32 + 255) / 256, 256>>>((const float4*)p_h, att1, 256);
    agg_kernel<128><<<NN, 256>>>(p_h, p_csrc, p_rowptr, p_si, p_sj,
                                 p_invdeg, b1, p_mu0, p_acc + 0, p_acc + 4);
    // -------- layer 1, t = 1 --------
    gemm_kernel<<<dim3(256 / BN, (NN + BM - 1) / BM), 256>>>(
        x_all + (size_t)NN * KDIM, W1, p_h, NN, 256);
    scores_kernel<<<(NN * 32 + 255) / 256, 256>>>((const float4*)p_h, att1, 256);
    agg_kernel<128><<<NN, 256>>>(p_h, p_csrc + EE, p_rowptr + (NN + 1), p_si, p_sj,
                                 p_invdeg + NN, b1, p_mu1, p_acc + 1, p_acc + 5);
    fuse1_kernel<<<(NN * 128 + 255) / 256, 256>>>();

    // -------- layer 2 (C = 64) --------
    for (int t = 0; t < TT; t++) {
        const float* xin = t ? p_mu1 : p_mu0;
        gemm_kernel<<<dim3(128 / BN, (NN + BM - 1) / BM), 256>>>(xin, W2, p_h, NN, 128);
        scores_kernel<<<(NN * 32 + 255) / 256, 256>>>((const float4*)p_h, att2, 128);
        agg_kernel<64><<<NN, 128>>>(p_h, p_csrc + (size_t)t * EE,
                                    p_rowptr + (size_t)t * (NN + 1), p_si, p_sj,
                                    p_invdeg + (size_t)t * NN, b2,
                                    t ? p_mu1 : out, p_acc + 2 + t, p_acc + 6 + t);
    }
    fuse2_kernel<<<(NN * 64 + 255) / 256, 256>>>(out);
    finalize_kernel<<<1, 1>>>(out, out_size);
}

// round 7
// speedup vs baseline: 1.2745x; 1.0885x over previous
#include <cuda_runtime.h>
#include <math.h>

#define NN 30000
#define EE 510000      // 30000*16 + 30000 self loops
#define TT 2
#define KDIM 128       // F_IN == H1 == 128 (GEMM K for both layers)

// ---------------- scratch (device globals; no allocation allowed) ----------------
__device__ float  g_h[(size_t)NN * 256];     // GEMM output t0, max 2C = 256
__device__ float  g_h2[(size_t)NN * 256];    // GEMM output t1
__device__ float  g_mu0[(size_t)NN * 128];   // layer outputs / fused inputs
__device__ float  g_mu1[(size_t)NN * 128];
__device__ float  g_alpha[TT][EE];
__device__ float  g_si[TT][NN];
__device__ float  g_sj[TT][NN];
__device__ float  g_invdeg[TT][NN];
__device__ int    g_deg[TT][NN];
__device__ int    g_rowptr[TT][NN + 1];
__device__ int    g_woff[TT][NN];
__device__ int    g_csrc[TT][EE];
__device__ int    g_cdst[TT][EE];
__device__ double g_acc[8];  // [0..3] ixz sums, [4..7] skl sums

// ---------------- helpers ----------------
__device__ __forceinline__ float blockReduceSum(float v, float* sm) {
    int lane = threadIdx.x & 31, wid = threadIdx.x >> 5;
#pragma unroll
    for (int o = 16; o; o >>= 1) v += __shfl_down_sync(0xffffffffu, v, o);
    if (lane == 0) sm[wid] = v;
    __syncthreads();
    int nw = (blockDim.x + 31) >> 5;
    v = (threadIdx.x < nw) ? sm[threadIdx.x] : 0.f;
    if (wid == 0) {
#pragma unroll
        for (int o = 16; o; o >>= 1) v += __shfl_down_sync(0xffffffffu, v, o);
    }
    return v;  // valid on thread 0
}

// ---------------- setup kernels ----------------
__global__ void zero_kernel() {
    int i = blockIdx.x * blockDim.x + threadIdx.x;
    if (i < TT * NN) (&g_deg[0][0])[i] = 0;
    if (i < 8) g_acc[i] = 0.0;
}

__global__ void hist_kernel(const int* __restrict__ dst, int t) {
    int e = blockIdx.x * blockDim.x + threadIdx.x;
    if (e < EE) atomicAdd(&g_deg[t][dst[e]], 1);
}

__global__ void scan_kernel(int t) {
    const int T = 1024;
    int tid = threadIdx.x;
    const int chunk = (NN + T - 1) / T;  // 30
    int s0 = tid * chunk;
    int sum = 0;
    for (int i = 0; i < chunk; i++) {
        int idx = s0 + i;
        if (idx < NN) sum += g_deg[t][idx];
    }
    int lane = tid & 31, wid = tid >> 5;
    int v = sum;
#pragma unroll
    for (int o = 1; o < 32; o <<= 1) {
        int u = __shfl_up_sync(0xffffffffu, v, o);
        if (lane >= o) v += u;
    }
    __shared__ int ws[32];
    if (lane == 31) ws[wid] = v;
    __syncthreads();
    if (wid == 0) {
        int w = ws[lane];
#pragma unroll
        for (int o = 1; o < 32; o <<= 1) {
            int u = __shfl_up_sync(0xffffffffu, w, o);
            if (lane >= o) w += u;
        }
        ws[lane] = w;
    }
    __syncthreads();
    int excl = (v - sum) + (wid > 0 ? ws[wid - 1] : 0);
    int run = excl;
    for (int i = 0; i < chunk; i++) {
        int idx = s0 + i;
        if (idx < NN) {
            int d = g_deg[t][idx];
            g_rowptr[t][idx] = run;
            g_woff[t][idx] = run;
            g_invdeg[t][idx] = 1.0f / (float)d;
            run += d;
        }
    }
    if (tid == T - 1) g_rowptr[t][NN] = run;
}

__global__ void scatter_kernel(const int* __restrict__ src, const int* __restrict__ dst, int t) {
    int e = blockIdx.x * blockDim.x + threadIdx.x;
    if (e < EE) {
        int d = dst[e];
        int pos = atomicAdd(&g_woff[t][d], 1);
        g_csrc[t][pos] = src[e];
        g_cdst[t][pos] = d;
    }
}

// ---------------- GEMM: C[M, Ncols] = A[M,128] * B[128, Ncols] ----------------
// 128x64 tile per block, BK=16, 256 threads, 4x8 per thread (A/B variable this round).
#define BM 128
#define BN 64
#define BK 16
__global__ void __launch_bounds__(256)
gemm_kernel(const float* __restrict__ A, const float* __restrict__ B,
            float* __restrict__ C, int M, int Ncols) {
    __shared__ float As[BK][BM];
    __shared__ float Bs[BK][BN];
    int tid = threadIdx.x;
    int tx = tid & 7;         // 0..7  -> col group of 8
    int ty = tid >> 3;        // 0..31 -> row group of 4
    int row0 = blockIdx.y * BM;
    int col0 = blockIdx.x * BN;
    int a_row = tid >> 1;         // 0..127
    int a_k   = (tid & 1) * 4;    // 0 or 4
    int b_k   = tid >> 4;         // 0..15
    int b_n   = (tid & 15) * 4;
    bool a_ok = (row0 + a_row) < M;
    const float* Aptr = A + (size_t)(row0 + a_row) * KDIM;
    const float* Bptr = B + (size_t)b_k * Ncols + col0 + b_n;

    float acc[4][8] = {};
    float4 z4 = make_float4(0.f, 0.f, 0.f, 0.f);
    float4 av0 = a_ok ? *(const float4*)(Aptr + a_k) : z4;
    float4 av1 = a_ok ? *(const float4*)(Aptr + a_k + 8) : z4;
    float4 bv = *(const float4*)Bptr;

    for (int k0 = 0; k0 < KDIM; k0 += BK) {
        As[a_k + 0][a_row] = av0.x;
        As[a_k + 1][a_row] = av0.y;
        As[a_k + 2][a_row] = av0.z;
        As[a_k + 3][a_row] = av0.w;
        As[a_k + 8][a_row] = av1.x;
        As[a_k + 9][a_row] = av1.y;
        As[a_k + 10][a_row] = av1.z;
        As[a_k + 11][a_row] = av1.w;
        *(float4*)&Bs[b_k][b_n] = bv;
        __syncthreads();
        if (k0 + BK < KDIM) {
            if (a_ok) {
                av0 = *(const float4*)(Aptr + k0 + BK + a_k);
                av1 = *(const float4*)(Aptr + k0 + BK + a_k + 8);
            }
            bv = *(const float4*)(Bptr + (size_t)(k0 + BK) * Ncols);
        }
#pragma unroll
        for (int k = 0; k < BK; k++) {
            float a[4], b[8];
            *(float4*)&a[0] = *(const float4*)&As[k][ty * 4];
            *(float4*)&b[0] = *(const float4*)&Bs[k][tx * 8];
            *(float4*)&b[4] = *(const float4*)&Bs[k][tx * 8 + 4];
#pragma unroll
            for (int i = 0; i < 4; i++)
#pragma unroll
                for (int j = 0; j < 8; j++) acc[i][j] = fmaf(a[i], b[j], acc[i][j]);
        }
        __syncthreads();
    }
#pragma unroll
    for (int i = 0; i < 4; i++) {
        int r = row0 + ty * 4 + i;
        if (r < M) {
            *(float4*)&C[(size_t)r * Ncols + col0 + tx * 8] =
                make_float4(acc[i][0], acc[i][1], acc[i][2], acc[i][3]);
            *(float4*)&C[(size_t)r * Ncols + col0 + tx * 8 + 4] =
                make_float4(acc[i][4], acc[i][5], acc[i][6], acc[i][7]);
        }
    }
}

// ---------------- per-node attention scores ----------------
__global__ void scores_kernel(const float4* __restrict__ h4, const float* __restrict__ att,
                              int TC, float* __restrict__ si, float* __restrict__ sj) {
    int gw = (blockIdx.x * blockDim.x + threadIdx.x) >> 5;
    int lane = threadIdx.x & 31;
    if (gw >= NN) return;
    int n4 = TC >> 2;
    const float4* row = h4 + (size_t)gw * n4;
    float a = 0.f, b = 0.f;
    for (int i = lane; i < n4; i += 32) {
        float4 v = row[i];
        a = fmaf(v.x, att[i * 4 + 0], a);
        a = fmaf(v.y, att[i * 4 + 1], a);
        a = fmaf(v.z, att[i * 4 + 2], a);
        a = fmaf(v.w, att[i * 4 + 3], a);
        b = fmaf(v.x, att[TC + i * 4 + 0], b);
        b = fmaf(v.y, att[TC + i * 4 + 1], b);
        b = fmaf(v.z, att[TC + i * 4 + 2], b);
        b = fmaf(v.w, att[TC + i * 4 + 3], b);
    }
#pragma unroll
    for (int o = 16; o; o >>= 1) {
        a += __shfl_down_sync(0xffffffffu, a, o);
        b += __shfl_down_sync(0xffffffffu, b, o);
    }
    if (lane == 0) {
        si[gw] = a;
        sj[gw] = b;
    }
}

// ---------------- per-edge alpha + skl (round-1 structure) ----------------
__global__ void alpha_kernel(int t, const float* __restrict__ si, const float* __restrict__ sj,
                             float* __restrict__ alpha, double* __restrict__ skl_slot) {
    __shared__ float s_red[32];
    int e = blockIdx.x * blockDim.x + threadIdx.x;
    float skl = 0.f;
    if (e < EE) {
        int d = g_cdst[t][e], s = g_csrc[t][e];
        float l = si[d] + sj[s];
        l = l > 0.f ? l : 0.2f * l;
        float p = 1.f / (1.f + expf(-l));
        p = fminf(fmaxf(p, 0.01f), 0.99f);
        alpha[e] = p * g_invdeg[t][d];
        float q = 1.0f / (1.0f + expf(-(1.0f / 15.0f)));
        skl = p * (logf(p) - logf(q)) + (1.f - p) * (logf(1.f - p) - logf(1.f - q));
    }
    float tot = blockReduceSum(skl, s_red);
    if (threadIdx.x == 0) atomicAdd(skl_slot, (double)tot);
}

// ---------------- aggregation + KL epilogue (round-1 shape) ----------------
template <int C>
__global__ void agg_kernel(const float* __restrict__ h, const float* __restrict__ alpha,
                           const int* __restrict__ csrc, const int* __restrict__ rowptr,
                           const float* __restrict__ bias, float* __restrict__ mu_out,
                           double* __restrict__ acc_slot) {
    constexpr int TC = 2 * C;
    __shared__ float s_alpha[TC];
    __shared__ int s_src[TC];
    __shared__ float s_std[C];
    __shared__ float s_red[32];
    int n = blockIdx.x, tid = threadIdx.x;
    int start = rowptr[n], end = rowptr[n + 1];
    float acc = 0.f;
    for (int base = start; base < end; base += TC) {
        int cnt = min(TC, end - base);
        if (tid < cnt) {
            s_alpha[tid] = alpha[base + tid];
            s_src[tid] = csrc[base + tid];
        }
        __syncthreads();
        for (int i = 0; i < cnt; i++)
            acc = fmaf(s_alpha[i], h[(size_t)s_src[i] * TC + tid], acc);
        __syncthreads();
    }
    acc += bias[tid];
    if (tid >= C) {
        float x = acc;
        s_std[tid - C] = fmaxf(x, 0.f) + log1pf(expf(-fabsf(x))) + 1e-10f;
    }
    __syncthreads();
    float kl = 0.f;
    if (tid < C) {
        float mu = acc, sd = s_std[tid];
        kl = -logf(sd) + 0.5f * fmaf(sd, sd, mu * mu) - 0.5f;
        mu_out[(size_t)n * C + tid] = mu;
    }
    float tot = blockReduceSum(kl, s_red);
    if (tid == 0) atomicAdd(acc_slot, (double)tot);
}

// ---------------- temporal fusion / activations ----------------
__global__ void fuse1_kernel() {
    int i = blockIdx.x * blockDim.x + threadIdx.x;
    if (i < NN * 128) {
        float m0 = g_mu0[i], m1 = g_mu1[i];
        g_mu1[i] = fmaxf(0.4f * m0 + 0.2f * m1, 0.f);  // h1[1] = relu(0.4*mu0 + 0.2*mu1)
        g_mu0[i] = fmaxf(m0, 0.f);                      // h1[0] = relu(mu0)
    }
}

__global__ void fuse2_kernel(float* __restrict__ out) {
    int i = blockIdx.x * blockDim.x + threadIdx.x;
    if (i < NN * 64) out[NN * 64 + i] = 0.4f * out[i] + 0.2f * g_mu1[i];
}

__global__ void finalize_kernel(float* __restrict__ out, int out_size) {
    double ixz = (g_acc[0] + g_acc[1] + g_acc[2] + g_acc[3]) / (4.0 * (double)NN);
    double skl = (g_acc[4] + g_acc[5] + g_acc[6] + g_acc[7]) / (4.0 * (double)EE);
    out[out_size - 2] = (float)ixz;
    out[out_size - 1] = (float)skl;
}

// ---------------- launch ----------------
extern "C" void kernel_launch(void* const* d_in, const int* in_sizes, int n_in,
                              void* d_out, int out_size) {
    const float* x_all = (const float*)d_in[0];   // [T, N, 128]
    const int* ei = (const int*)d_in[1];          // [T, 2, E]
    const float* W1 = (const float*)d_in[2];      // [128, 256]
    const float* att1 = (const float*)d_in[3];    // [512]
    const float* b1 = (const float*)d_in[4];      // [256]
    const float* W2 = (const float*)d_in[5];      // [128, 128]
    const float* att2 = (const float*)d_in[6];    // [256]
    const float* b2 = (const float*)d_in[7];      // [128]
    float* out = (float*)d_out;

    float *p_h, *p_h2, *p_mu0, *p_mu1, *p_si, *p_sj, *p_invdeg, *p_alpha;
    int *p_csrc, *p_rowptr;
    double* p_acc;
    cudaGetSymbolAddress((void**)&p_h, g_h);
    cudaGetSymbolAddress((void**)&p_h2, g_h2);
    cudaGetSymbolAddress((void**)&p_mu0, g_mu0);
    cudaGetSymbolAddress((void**)&p_mu1, g_mu1);
    cudaGetSymbolAddress((void**)&p_si, g_si);
    cudaGetSymbolAddress((void**)&p_sj, g_sj);
    cudaGetSymbolAddress((void**)&p_invdeg, g_invdeg);
    cudaGetSymbolAddress((void**)&p_alpha, g_alpha);
    cudaGetSymbolAddress((void**)&p_csrc, g_csrc);
    cudaGetSymbolAddress((void**)&p_rowptr, g_rowptr);
    cudaGetSymbolAddress((void**)&p_acc, g_acc);

    const int EB = (EE + 255) / 256;
    const int SB = (NN * 32 + 255) / 256;
    const int* src0 = ei;
    const int* dst0 = ei + EE;
    const int* src1 = ei + (size_t)2 * EE;
    const int* dst1 = ei + (size_t)3 * EE;

    // Launch indices 3 and 6 are both layer-1 GEMMs so ncu's bounded capture
    // (observed landing at an early setup-phase index) hits the dominant kernel.
    zero_kernel<<<(TT * NN + 255) / 256, 256>>>();                         // 0
    hist_kernel<<<EB, 256>>>(dst0, 0);                                     // 1
    scan_kernel<<<1, 1024>>>(0);                                           // 2
    gemm_kernel<<<dim3(256 / BN, (NN + BM - 1) / BM), 256>>>(              // 3
        x_all, W1, p_h, NN, 256);
    hist_kernel<<<EB, 256>>>(dst1, 1);                                     // 4
    scan_kernel<<<1, 1024>>>(1);                                           // 5
    gemm_kernel<<<dim3(256 / BN, (NN + BM - 1) / BM), 256>>>(              // 6
        x_all + (size_t)NN * KDIM, W1, p_h2, NN, 256);
    scatter_kernel<<<EB, 256>>>(src0, dst0, 0);                            // 7
    scatter_kernel<<<EB, 256>>>(src1, dst1, 1);                            // 8

    // -------- layer 1 (C = 128) --------
    scores_kernel<<<SB, 256>>>((const float4*)p_h, att1, 256, p_si, p_sj);
    scores_kernel<<<SB, 256>>>((const float4*)p_h2, att1, 256, p_si + NN, p_sj + NN);
    alpha_kernel<<<EB, 256>>>(0, p_si, p_sj, p_alpha, p_acc + 4);
    alpha_kernel<<<EB, 256>>>(1, p_si + NN, p_sj + NN, p_alpha + EE, p_acc + 5);
    agg_kernel<128><<<NN, 256>>>(p_h, p_alpha, p_csrc, p_rowptr, b1,
                                 p_mu0, p_acc + 0);
    agg_kernel<128><<<NN, 256>>>(p_h2, p_alpha + EE, p_csrc + EE, p_rowptr + (NN + 1), b1,
                                 p_mu1, p_acc + 1);
    fuse1_kernel<<<(NN * 128 + 255) / 256, 256>>>();

    // -------- layer 2 (C = 64) --------
    for (int t = 0; t < TT; t++) {
        const float* xin = t ? p_mu1 : p_mu0;
        float* hbuf = t ? p_h2 : p_h;
        gemm_kernel<<<dim3(128 / BN, (NN + BM - 1) / BM), 256>>>(xin, W2, hbuf, NN, 128);
        scores_kernel<<<SB, 256>>>((const float4*)hbuf, att2, 128,
                                   p_si + (size_t)t * NN, p_sj + (size_t)t * NN);
        alpha_kernel<<<EB, 256>>>(t, p_si + (size_t)t * NN, p_sj + (size_t)t * NN,
                                  p_alpha + (size_t)t * EE, p_acc + 6 + t);
        agg_kernel<64><<<NN, 128>>>(hbuf, p_alpha + (size_t)t * EE, p_csrc + (size_t)t * EE,
                                    p_rowptr + (size_t)t * (NN + 1), b2,
                                    t ? p_mu1 : out, p_acc + 2 + t);
    }
    fuse2_kernel<<<(NN * 64 + 255) / 256, 256>>>(out);
    finalize_kernel<<<1, 1>>>(out, out_size);
}

// round 8
// speedup vs baseline: 1.3729x; 1.0772x over previous
#include <cuda_runtime.h>
#include <math.h>

#define NN 30000
#define EE 510000      // 30000*16 + 30000 self loops
#define TT 2
#define KDIM 128       // F_IN == H1 == 128 (GEMM K for both layers)

// ---------------- scratch (device globals; no allocation allowed) ----------------
__device__ float  g_h[(size_t)NN * 256];     // GEMM output, max 2C = 256
__device__ float  g_mu0[(size_t)NN * 128];   // layer outputs / fused inputs
__device__ float  g_mu1[(size_t)NN * 128];
__device__ float  g_alpha[EE];
__device__ float  g_si[NN];
__device__ float  g_sj[NN];
__device__ float  g_watt[2][128];            // W @ att halves (per current layer)
__device__ float  g_invdeg[TT][NN];
__device__ int    g_deg[TT][NN];
__device__ int    g_rowptr[TT][NN + 1];
__device__ int    g_woff[TT][NN];
__device__ int    g_csrc[TT][EE];
__device__ int    g_cdst[TT][EE];
__device__ double g_acc[8];  // [0..3] ixz sums, [4..7] skl sums

// ---------------- helpers ----------------
__device__ __forceinline__ float blockReduceSum(float v, float* sm) {
    int lane = threadIdx.x & 31, wid = threadIdx.x >> 5;
#pragma unroll
    for (int o = 16; o; o >>= 1) v += __shfl_down_sync(0xffffffffu, v, o);
    if (lane == 0) sm[wid] = v;
    __syncthreads();
    int nw = (blockDim.x + 31) >> 5;
    v = (threadIdx.x < nw) ? sm[threadIdx.x] : 0.f;
    if (wid == 0) {
#pragma unroll
        for (int o = 16; o; o >>= 1) v += __shfl_down_sync(0xffffffffu, v, o);
    }
    return v;  // valid on thread 0
}

// ---------------- setup kernels ----------------
__global__ void zero_kernel() {
    int i = blockIdx.x * blockDim.x + threadIdx.x;
    if (i < TT * NN) (&g_deg[0][0])[i] = 0;
    if (i < 8) g_acc[i] = 0.0;
}

__global__ void hist_kernel(const int* __restrict__ dst, int t) {
    int e = blockIdx.x * blockDim.x + threadIdx.x;
    if (e < EE) atomicAdd(&g_deg[t][dst[e]], 1);
}

__global__ void scan_kernel(int t) {
    const int T = 1024;
    int tid = threadIdx.x;
    const int chunk = (NN + T - 1) / T;  // 30
    int s0 = tid * chunk;
    int sum = 0;
    for (int i = 0; i < chunk; i++) {
        int idx = s0 + i;
        if (idx < NN) sum += g_deg[t][idx];
    }
    int lane = tid & 31, wid = tid >> 5;
    int v = sum;
#pragma unroll
    for (int o = 1; o < 32; o <<= 1) {
        int u = __shfl_up_sync(0xffffffffu, v, o);
        if (lane >= o) v += u;
    }
    __shared__ int ws[32];
    if (lane == 31) ws[wid] = v;
    __syncthreads();
    if (wid == 0) {
        int w = ws[lane];
#pragma unroll
        for (int o = 1; o < 32; o <<= 1) {
            int u = __shfl_up_sync(0xffffffffu, w, o);
            if (lane >= o) w += u;
        }
        ws[lane] = w;
    }
    __syncthreads();
    int excl = (v - sum) + (wid > 0 ? ws[wid - 1] : 0);
    int run = excl;
    for (int i = 0; i < chunk; i++) {
        int idx = s0 + i;
        if (idx < NN) {
            int d = g_deg[t][idx];
            g_rowptr[t][idx] = run;
            g_woff[t][idx] = run;
            g_invdeg[t][idx] = 1.0f / (float)d;
            run += d;
        }
    }
    if (tid == T - 1) g_rowptr[t][NN] = run;
}

__global__ void scatter_kernel(const int* __restrict__ src, const int* __restrict__ dst, int t) {
    int e = blockIdx.x * blockDim.x + threadIdx.x;
    if (e < EE) {
        int d = dst[e];
        int pos = atomicAdd(&g_woff[t][d], 1);
        g_csrc[t][pos] = src[e];
        g_cdst[t][pos] = d;
    }
}

// ---------------- GEMM: C[M, Ncols] = A[M,128] * B[128, Ncols] ----------------
// 128x128 tile per block, 256 threads, 8x8 per thread, BK=8, global prefetch.
// Per k-step per thread: 64 FFMA vs 4 LDS.128 -> FMA:LDS cycle ratio 2:1.
__global__ void __launch_bounds__(256, 2)
gemm_kernel(const float* __restrict__ A, const float* __restrict__ B,
            float* __restrict__ C, int M, int Ncols) {
    __shared__ float As[8][128];
    __shared__ float Bs[8][128];
    int tid = threadIdx.x;
    int tx = tid & 15;        // 0..15 -> col group of 8
    int ty = tid >> 4;        // 0..15 -> row group of 8
    int row0 = blockIdx.y * 128;
    int col0 = blockIdx.x * 128;
    int a_row = tid >> 1;           // 0..127
    int a_k   = (tid & 1) * 4;      // 0 or 4
    int b_k   = tid >> 5;           // 0..7
    int b_n   = (tid & 31) * 4;
    bool a_ok = (row0 + a_row) < M;
    const float* Aptr = A + (size_t)(row0 + a_row) * KDIM + a_k;
    const float* Bptr = B + (size_t)b_k * Ncols + col0 + b_n;

    float acc[8][8] = {};
    float4 av = a_ok ? *(const float4*)Aptr : make_float4(0.f, 0.f, 0.f, 0.f);
    float4 bv = *(const float4*)Bptr;

    for (int k0 = 0; k0 < KDIM; k0 += 8) {
        As[a_k + 0][a_row] = av.x;
        As[a_k + 1][a_row] = av.y;
        As[a_k + 2][a_row] = av.z;
        As[a_k + 3][a_row] = av.w;
        *(float4*)&Bs[b_k][b_n] = bv;
        __syncthreads();
        if (k0 + 8 < KDIM) {
            if (a_ok) av = *(const float4*)(Aptr + k0 + 8);
            bv = *(const float4*)(Bptr + (size_t)(k0 + 8) * Ncols);
        }
#pragma unroll
        for (int k = 0; k < 8; k++) {
            float a[8], b[8];
            *(float4*)&a[0] = *(const float4*)&As[k][ty * 8];
            *(float4*)&a[4] = *(const float4*)&As[k][ty * 8 + 4];
            *(float4*)&b[0] = *(const float4*)&Bs[k][tx * 8];
            *(float4*)&b[4] = *(const float4*)&Bs[k][tx * 8 + 4];
#pragma unroll
            for (int i = 0; i < 8; i++)
#pragma unroll
                for (int j = 0; j < 8; j++) acc[i][j] = fmaf(a[i], b[j], acc[i][j]);
        }
        __syncthreads();
    }
#pragma unroll
    for (int i = 0; i < 8; i++) {
        int r = row0 + ty * 8 + i;
        if (r < M) {
            *(float4*)&C[(size_t)r * Ncols + col0 + tx * 8] =
                make_float4(acc[i][0], acc[i][1], acc[i][2], acc[i][3]);
            *(float4*)&C[(size_t)r * Ncols + col0 + tx * 8 + 4] =
                make_float4(acc[i][4], acc[i][5], acc[i][6], acc[i][7]);
        }
    }
}

// ---------------- W @ att precompute: w[2][128] ----------------
// w[0][k] = sum_c W[k][c]*att[c];  w[1][k] = sum_c W[k][c]*att[TC+c]
__global__ void watt_kernel(const float* __restrict__ W, const float* __restrict__ att, int TC) {
    int k = threadIdx.x;  // 0..127
    const float* row = W + (size_t)k * TC;
    float a = 0.f, b = 0.f;
    for (int c = 0; c < TC; c++) {
        float v = row[c];
        a = fmaf(v, att[c], a);
        b = fmaf(v, att[TC + c], b);
    }
    g_watt[0][k] = a;
    g_watt[1][k] = b;
}

// ---------------- per-node attention scores from layer INPUT x ----------------
// si[n] = x[n] . w[0], sj[n] = x[n] . w[1]   (x is the 128-wide layer input)
__global__ void scores_x_kernel(const float4* __restrict__ x4) {
    int gw = (blockIdx.x * blockDim.x + threadIdx.x) >> 5;
    int lane = threadIdx.x & 31;
    if (gw >= NN) return;
    float4 v = x4[(size_t)gw * 32 + lane];
    const float4 wa = *(const float4*)&g_watt[0][lane * 4];
    const float4 wb = *(const float4*)&g_watt[1][lane * 4];
    float a = v.x * wa.x + v.y * wa.y + v.z * wa.z + v.w * wa.w;
    float b = v.x * wb.x + v.y * wb.y + v.z * wb.z + v.w * wb.w;
#pragma unroll
    for (int o = 16; o; o >>= 1) {
        a += __shfl_down_sync(0xffffffffu, a, o);
        b += __shfl_down_sync(0xffffffffu, b, o);
    }
    if (lane == 0) {
        g_si[gw] = a;
        g_sj[gw] = b;
    }
}

// ---------------- per-edge alpha + skl ----------------
__global__ void alpha_kernel(int t, double* __restrict__ skl_slot) {
    __shared__ float s_red[32];
    int e = blockIdx.x * blockDim.x + threadIdx.x;
    float skl = 0.f;
    if (e < EE) {
        int d = g_cdst[t][e], s = g_csrc[t][e];
        float l = g_si[d] + g_sj[s];
        l = l > 0.f ? l : 0.2f * l;
        float p = 1.f / (1.f + expf(-l));
        p = fminf(fmaxf(p, 0.01f), 0.99f);
        g_alpha[e] = p * g_invdeg[t][d];
        float q = 1.0f / (1.0f + expf(-(1.0f / 15.0f)));
        skl = p * (logf(p) - logf(q)) + (1.f - p) * (logf(1.f - p) - logf(1.f - q));
    }
    float tot = blockReduceSum(skl, s_red);
    if (threadIdx.x == 0) atomicAdd(skl_slot, (double)tot);
}

// ---------------- aggregation + KL epilogue (round-1 shape) ----------------
template <int C>
__global__ void agg_kernel(const float* __restrict__ h, const float* __restrict__ alpha,
                           const int* __restrict__ csrc, const int* __restrict__ rowptr,
                           const float* __restrict__ bias, float* __restrict__ mu_out,
                           double* __restrict__ acc_slot) {
    constexpr int TC = 2 * C;
    __shared__ float s_alpha[TC];
    __shared__ int s_src[TC];
    __shared__ float s_std[C];
    __shared__ float s_red[32];
    int n = blockIdx.x, tid = threadIdx.x;
    int start = rowptr[n], end = rowptr[n + 1];
    float acc = 0.f;
    for (int base = start; base < end; base += TC) {
        int cnt = min(TC, end - base);
        if (tid < cnt) {
            s_alpha[tid] = alpha[base + tid];
            s_src[tid] = csrc[base + tid];
        }
        __syncthreads();
        for (int i = 0; i < cnt; i++)
            acc = fmaf(s_alpha[i], h[(size_t)s_src[i] * TC + tid], acc);
        __syncthreads();
    }
    acc += bias[tid];
    if (tid >= C) {
        float x = acc;
        s_std[tid - C] = fmaxf(x, 0.f) + log1pf(expf(-fabsf(x))) + 1e-10f;
    }
    __syncthreads();
    float kl = 0.f;
    if (tid < C) {
        float mu = acc, sd = s_std[tid];
        kl = -logf(sd) + 0.5f * fmaf(sd, sd, mu * mu) - 0.5f;
        mu_out[(size_t)n * C + tid] = mu;
    }
    float tot = blockReduceSum(kl, s_red);
    if (tid == 0) atomicAdd(acc_slot, (double)tot);
}

// ---------------- temporal fusion / activations ----------------
__global__ void fuse1_kernel() {
    int i = blockIdx.x * blockDim.x + threadIdx.x;
    if (i < NN * 128) {
        float m0 = g_mu0[i], m1 = g_mu1[i];
        g_mu1[i] = fmaxf(0.4f * m0 + 0.2f * m1, 0.f);  // h1[1] = relu(0.4*mu0 + 0.2*mu1)
        g_mu0[i] = fmaxf(m0, 0.f);                      // h1[0] = relu(mu0)
    }
}

__global__ void fuse2_kernel(float* __restrict__ out) {
    int i = blockIdx.x * blockDim.x + threadIdx.x;
    if (i < NN * 64) out[NN * 64 + i] = 0.4f * out[i] + 0.2f * g_mu1[i];
}

__global__ void finalize_kernel(float* __restrict__ out, int out_size) {
    double ixz = (g_acc[0] + g_acc[1] + g_acc[2] + g_acc[3]) / (4.0 * (double)NN);
    double skl = (g_acc[4] + g_acc[5] + g_acc[6] + g_acc[7]) / (4.0 * (double)EE);
    out[out_size - 2] = (float)ixz;
    out[out_size - 1] = (float)skl;
}

// ---------------- launch ----------------
extern "C" void kernel_launch(void* const* d_in, const int* in_sizes, int n_in,
                              void* d_out, int out_size) {
    const float* x_all = (const float*)d_in[0];   // [T, N, 128]
    const int* ei = (const int*)d_in[1];          // [T, 2, E]
    const float* W1 = (const float*)d_in[2];      // [128, 256]
    const float* att1 = (const float*)d_in[3];    // [512]
    const float* b1 = (const float*)d_in[4];      // [256]
    const float* W2 = (const float*)d_in[5];      // [128, 128]
    const float* att2 = (const float*)d_in[6];    // [256]
    const float* b2 = (const float*)d_in[7];      // [128]
    float* out = (float*)d_out;

    float *p_h, *p_mu0, *p_mu1, *p_alpha;
    int *p_csrc, *p_rowptr;
    double* p_acc;
    cudaGetSymbolAddress((void**)&p_h, g_h);
    cudaGetSymbolAddress((void**)&p_mu0, g_mu0);
    cudaGetSymbolAddress((void**)&p_mu1, g_mu1);
    cudaGetSymbolAddress((void**)&p_alpha, g_alpha);
    cudaGetSymbolAddress((void**)&p_csrc, g_csrc);
    cudaGetSymbolAddress((void**)&p_rowptr, g_rowptr);
    cudaGetSymbolAddress((void**)&p_acc, g_acc);

    const int EB = (EE + 255) / 256;
    const int SB = (NN * 32 + 255) / 256;
    const int* src0 = ei;
    const int* dst0 = ei + EE;
    const int* src1 = ei + (size_t)2 * EE;
    const int* dst1 = ei + (size_t)3 * EE;

    // GEMM at launch index 3 (where ncu's bounded capture lands).
    zero_kernel<<<(TT * NN + 255) / 256, 256>>>();                      // 0
    hist_kernel<<<EB, 256>>>(dst0, 0);                                  // 1
    scan_kernel<<<1, 1024>>>(0);                                        // 2
    gemm_kernel<<<dim3(2, (NN + 127) / 128), 256>>>(x_all, W1, p_h, NN, 256);  // 3
    scatter_kernel<<<EB, 256>>>(src0, dst0, 0);                         // 4
    hist_kernel<<<EB, 256>>>(dst1, 1);                                  // 5
    scan_kernel<<<1, 1024>>>(1);                                        // 6
    scatter_kernel<<<EB, 256>>>(src1, dst1, 1);                         // 7
    watt_kernel<<<1, 128>>>(W1, att1, 256);                             // 8

    // -------- layer 1 (C = 128), t = 0 (GEMM already done) --------
    scores_x_kernel<<<SB, 256>>>((const float4*)x_all);
    alpha_kernel<<<EB, 256>>>(0, p_acc + 4);
    agg_kernel<128><<<NN, 256>>>(p_h, p_alpha, p_csrc, p_rowptr, b1, p_mu0, p_acc + 0);
    // -------- layer 1, t = 1 --------
    gemm_kernel<<<dim3(2, (NN + 127) / 128), 256>>>(x_all + (size_t)NN * KDIM, W1, p_h, NN, 256);
    scores_x_kernel<<<SB, 256>>>((const float4*)(x_all + (size_t)NN * KDIM));
    alpha_kernel<<<EB, 256>>>(1, p_acc + 5);
    agg_kernel<128><<<NN, 256>>>(p_h, p_alpha, p_csrc + EE, p_rowptr + (NN + 1), b1,
                                 p_mu1, p_acc + 1);
    fuse1_kernel<<<(NN * 128 + 255) / 256, 256>>>();

    // -------- layer 2 (C = 64) --------
    watt_kernel<<<1, 128>>>(W2, att2, 128);
    for (int t = 0; t < TT; t++) {
        const float* xin = t ? p_mu1 : p_mu0;
        gemm_kernel<<<dim3(1, (NN + 127) / 128), 256>>>(xin, W2, p_h, NN, 128);
        scores_x_kernel<<<SB, 256>>>((const float4*)xin);
        alpha_kernel<<<EB, 256>>>(t, p_acc + 6 + t);
        agg_kernel<64><<<NN, 128>>>(p_h, p_alpha, p_csrc + (size_t)t * EE,
                                    p_rowptr + (size_t)t * (NN + 1), b2,
                                    t ? p_mu1 : out, p_acc + 2 + t);
    }
    fuse2_kernel<<<(NN * 64 + 255) / 256, 256>>>(out);
    finalize_kernel<<<1, 1>>>(out, out_size);
}

// round 9
// speedup vs baseline: 1.5654x; 1.1402x over previous
#include <cuda_runtime.h>
#include <math.h>
#include <stdint.h>

#define NN 30000
#define EE 510000      // 30000*16 + 30000 self loops
#define TT 2
#define KDIM 128       // F_IN == H1 == 128 (GEMM K for both layers)

// ---------------- scratch (device globals; no allocation allowed) ----------------
__device__ float  g_h[(size_t)NN * 256];     // GEMM output, max 2C = 256
__device__ float  g_mu0[(size_t)NN * 128];   // layer outputs / fused inputs
__device__ float  g_mu1[(size_t)NN * 128];
__device__ float  g_alpha[EE];
__device__ float  g_si[NN];
__device__ float  g_sj[NN];
__device__ float  g_watt[2][128];            // W @ att halves (per current layer)
__device__ float  g_invdeg[TT][NN];
__device__ int    g_deg[TT][NN];
__device__ int    g_rowptr[TT][NN + 1];
__device__ int    g_woff[TT][NN];
__device__ int    g_csrc[TT][EE];
__device__ int    g_cdst[TT][EE];
__device__ double g_acc[8];  // [0..3] ixz sums, [4..7] skl sums

// ---------------- helpers ----------------
__device__ __forceinline__ float blockReduceSum(float v, float* sm) {
    int lane = threadIdx.x & 31, wid = threadIdx.x >> 5;
#pragma unroll
    for (int o = 16; o; o >>= 1) v += __shfl_down_sync(0xffffffffu, v, o);
    if (lane == 0) sm[wid] = v;
    __syncthreads();
    int nw = (blockDim.x + 31) >> 5;
    v = (threadIdx.x < nw) ? sm[threadIdx.x] : 0.f;
    if (wid == 0) {
#pragma unroll
        for (int o = 16; o; o >>= 1) v += __shfl_down_sync(0xffffffffu, v, o);
    }
    return v;  // valid on thread 0
}

__device__ __forceinline__ uint32_t f2tf32(float f) {
    uint32_t u;
    asm("cvt.rna.tf32.f32 %0, %1;" : "=r"(u) : "f"(f));
    return u;
}

// ---------------- setup kernels ----------------
__global__ void zero_kernel() {
    int i = blockIdx.x * blockDim.x + threadIdx.x;
    if (i < TT * NN) (&g_deg[0][0])[i] = 0;
    if (i < 8) g_acc[i] = 0.0;
}

__global__ void hist_kernel(const int* __restrict__ dst, int t) {
    int e = blockIdx.x * blockDim.x + threadIdx.x;
    if (e < EE) atomicAdd(&g_deg[t][dst[e]], 1);
}

__global__ void scan_kernel(int t) {
    const int T = 1024;
    int tid = threadIdx.x;
    const int chunk = (NN + T - 1) / T;  // 30
    int s0 = tid * chunk;
    int sum = 0;
    for (int i = 0; i < chunk; i++) {
        int idx = s0 + i;
        if (idx < NN) sum += g_deg[t][idx];
    }
    int lane = tid & 31, wid = tid >> 5;
    int v = sum;
#pragma unroll
    for (int o = 1; o < 32; o <<= 1) {
        int u = __shfl_up_sync(0xffffffffu, v, o);
        if (lane >= o) v += u;
    }
    __shared__ int ws[32];
    if (lane == 31) ws[wid] = v;
    __syncthreads();
    if (wid == 0) {
        int w = ws[lane];
#pragma unroll
        for (int o = 1; o < 32; o <<= 1) {
            int u = __shfl_up_sync(0xffffffffu, w, o);
            if (lane >= o) w += u;
        }
        ws[lane] = w;
    }
    __syncthreads();
    int excl = (v - sum) + (wid > 0 ? ws[wid - 1] : 0);
    int run = excl;
    for (int i = 0; i < chunk; i++) {
        int idx = s0 + i;
        if (idx < NN) {
            int d = g_deg[t][idx];
            g_rowptr[t][idx] = run;
            g_woff[t][idx] = run;
            g_invdeg[t][idx] = 1.0f / (float)d;
            run += d;
        }
    }
    if (tid == T - 1) g_rowptr[t][NN] = run;
}

__global__ void scatter_kernel(const int* __restrict__ src, const int* __restrict__ dst, int t) {
    int e = blockIdx.x * blockDim.x + threadIdx.x;
    if (e < EE) {
        int d = dst[e];
        int pos = atomicAdd(&g_woff[t][d], 1);
        g_csrc[t][pos] = src[e];
        g_cdst[t][pos] = d;
    }
}

// ---------------- TF32 tensor-core GEMM: C[M,Ncols] = A[M,128] * B[128,Ncols] ----
// Tile 128x64, BK=32, 256 threads (8 warps), each warp 32x32 via m16n8k8.
#define ASTR 36   // padded f32 stride (144B, 16B-aligned rows, bank-rotating)
__global__ void __launch_bounds__(256)
gemm_tc_kernel(const float* __restrict__ A, const float* __restrict__ B,
               float* __restrict__ C, int M, int Ncols) {
    __shared__ float As[128 * ASTR];
    __shared__ float Bs[64 * ASTR];
    int tid = threadIdx.x, lane = tid & 31, wid = tid >> 5;
    int warp_m = wid & 3;       // 4 warps over M (32 rows each)
    int warp_n = wid >> 2;      // 2 warps over N (32 cols each)
    int row0 = blockIdx.y * 128, col0 = blockIdx.x * 64;
    int sub = lane >> 3, l8 = lane & 7;

    uint32_t as_base = (uint32_t)__cvta_generic_to_shared(As);
    uint32_t bs_base = (uint32_t)__cvta_generic_to_shared(Bs);

    float acc[2][4][4];
#pragma unroll
    for (int i = 0; i < 2; i++)
#pragma unroll
        for (int j = 0; j < 4; j++)
#pragma unroll
            for (int k = 0; k < 4; k++) acc[i][j][k] = 0.f;

    // ldmatrix lane-address components (constant across k0)
    int a_r = warp_m * 32 + (sub & 1) * 8 + l8;       // + im*16
    int a_c = (sub >> 1) * 4;                          // + kk
    int b_r = warp_n * 32 + (sub >> 1) * 8 + l8;      // + p*16
    int b_c = (sub & 1) * 4;                           // + kk

    for (int k0 = 0; k0 < KDIM; k0 += 32) {
        // fill A tile (128x32), tf32-converted
#pragma unroll
        for (int i = 0; i < 4; i++) {
            int idx = tid + i * 256;          // 0..1023
            int r = idx >> 3, kc = (idx & 7) * 4;
            float4 v = make_float4(0.f, 0.f, 0.f, 0.f);
            if (row0 + r < M)
                v = *(const float4*)&A[(size_t)(row0 + r) * KDIM + k0 + kc];
            float4 w;
            w.x = __uint_as_float(f2tf32(v.x));
            w.y = __uint_as_float(f2tf32(v.y));
            w.z = __uint_as_float(f2tf32(v.z));
            w.w = __uint_as_float(f2tf32(v.w));
            *(float4*)&As[r * ASTR + kc] = w;
        }
        // fill B tile transposed: Bs[n][k]
#pragma unroll
        for (int i = 0; i < 8; i++) {
            int idx = tid + i * 256;          // 0..2047
            int k = idx >> 6, n = idx & 63;
            float v = B[(size_t)(k0 + k) * Ncols + col0 + n];
            Bs[n * ASTR + k] = __uint_as_float(f2tf32(v));
        }
        __syncthreads();
#pragma unroll
        for (int kk = 0; kk < 32; kk += 8) {
            uint32_t a[2][4], b[2][4];
#pragma unroll
            for (int im = 0; im < 2; im++) {
                uint32_t addr = as_base + (uint32_t)(((a_r + im * 16) * ASTR + a_c + kk) * 4);
                asm volatile("ldmatrix.sync.aligned.m8n8.x4.shared.b16 {%0,%1,%2,%3}, [%4];"
                             : "=r"(a[im][0]), "=r"(a[im][1]), "=r"(a[im][2]), "=r"(a[im][3])
                             : "r"(addr));
            }
#pragma unroll
            for (int p = 0; p < 2; p++) {
                uint32_t addr = bs_base + (uint32_t)(((b_r + p * 16) * ASTR + b_c + kk) * 4);
                asm volatile("ldmatrix.sync.aligned.m8n8.x4.shared.b16 {%0,%1,%2,%3}, [%4];"
                             : "=r"(b[p][0]), "=r"(b[p][1]), "=r"(b[p][2]), "=r"(b[p][3])
                             : "r"(addr));
            }
#pragma unroll
            for (int im = 0; im < 2; im++)
#pragma unroll
                for (int in = 0; in < 4; in++) {
                    uint32_t b0 = b[in >> 1][(in & 1) * 2 + 0];
                    uint32_t b1 = b[in >> 1][(in & 1) * 2 + 1];
                    asm volatile(
                        "mma.sync.aligned.m16n8k8.row.col.f32.tf32.tf32.f32 "
                        "{%0,%1,%2,%3}, {%4,%5,%6,%7}, {%8,%9}, {%0,%1,%2,%3};"
                        : "+f"(acc[im][in][0]), "+f"(acc[im][in][1]),
                          "+f"(acc[im][in][2]), "+f"(acc[im][in][3])
                        : "r"(a[im][0]), "r"(a[im][1]), "r"(a[im][2]), "r"(a[im][3]),
                          "r"(b0), "r"(b1));
                }
        }
        __syncthreads();
    }
    // epilogue
#pragma unroll
    for (int im = 0; im < 2; im++) {
        int r = row0 + warp_m * 32 + im * 16 + (lane >> 2);
#pragma unroll
        for (int in = 0; in < 4; in++) {
            int c = col0 + warp_n * 32 + in * 8 + (lane & 3) * 2;
            if (r < M)
                *(float2*)&C[(size_t)r * Ncols + c] = make_float2(acc[im][in][0], acc[im][in][1]);
            if (r + 8 < M)
                *(float2*)&C[(size_t)(r + 8) * Ncols + c] = make_float2(acc[im][in][2], acc[im][in][3]);
        }
    }
}

// ---------------- W @ att precompute: w[2][128] ----------------
__global__ void watt_kernel(const float* __restrict__ W, const float* __restrict__ att, int TC) {
    int k = threadIdx.x;  // 0..127
    const float* row = W + (size_t)k * TC;
    float a = 0.f, b = 0.f;
    for (int c = 0; c < TC; c++) {
        float v = row[c];
        a = fmaf(v, att[c], a);
        b = fmaf(v, att[TC + c], b);
    }
    g_watt[0][k] = a;
    g_watt[1][k] = b;
}

// ---------------- per-node attention scores from layer INPUT x ----------------
__global__ void scores_x_kernel(const float4* __restrict__ x4) {
    int gw = (blockIdx.x * blockDim.x + threadIdx.x) >> 5;
    int lane = threadIdx.x & 31;
    if (gw >= NN) return;
    float4 v = x4[(size_t)gw * 32 + lane];
    const float4 wa = *(const float4*)&g_watt[0][lane * 4];
    const float4 wb = *(const float4*)&g_watt[1][lane * 4];
    float a = v.x * wa.x + v.y * wa.y + v.z * wa.z + v.w * wa.w;
    float b = v.x * wb.x + v.y * wb.y + v.z * wb.z + v.w * wb.w;
#pragma unroll
    for (int o = 16; o; o >>= 1) {
        a += __shfl_down_sync(0xffffffffu, a, o);
        b += __shfl_down_sync(0xffffffffu, b, o);
    }
    if (lane == 0) {
        g_si[gw] = a;
        g_sj[gw] = b;
    }
}

// ---------------- per-edge alpha + skl ----------------
__global__ void alpha_kernel(int t, double* __restrict__ skl_slot) {
    __shared__ float s_red[32];
    int e = blockIdx.x * blockDim.x + threadIdx.x;
    float skl = 0.f;
    if (e < EE) {
        int d = g_cdst[t][e], s = g_csrc[t][e];
        float l = g_si[d] + g_sj[s];
        l = l > 0.f ? l : 0.2f * l;
        float p = 1.f / (1.f + expf(-l));
        p = fminf(fmaxf(p, 0.01f), 0.99f);
        g_alpha[e] = p * g_invdeg[t][d];
        float q = 1.0f / (1.0f + expf(-(1.0f / 15.0f)));
        skl = p * (logf(p) - logf(q)) + (1.f - p) * (logf(1.f - p) - logf(1.f - q));
    }
    float tot = blockReduceSum(skl, s_red);
    if (threadIdx.x == 0) atomicAdd(skl_slot, (double)tot);
}

// ---------------- aggregation + KL epilogue ----------------
template <int C>
__global__ void agg_kernel(const float* __restrict__ h, const float* __restrict__ alpha,
                           const int* __restrict__ csrc, const int* __restrict__ rowptr,
                           const float* __restrict__ bias, float* __restrict__ mu_out,
                           double* __restrict__ acc_slot) {
    constexpr int TC = 2 * C;
    __shared__ float s_alpha[TC];
    __shared__ int s_src[TC];
    __shared__ float s_std[C];
    __shared__ float s_red[32];
    int n = blockIdx.x, tid = threadIdx.x;
    int start = rowptr[n], end = rowptr[n + 1];
    float acc = 0.f;
    for (int base = start; base < end; base += TC) {
        int cnt = min(TC, end - base);
        if (tid < cnt) {
            s_alpha[tid] = alpha[base + tid];
            s_src[tid] = csrc[base + tid];
        }
        __syncthreads();
        for (int i = 0; i < cnt; i++)
            acc = fmaf(s_alpha[i], h[(size_t)s_src[i] * TC + tid], acc);
        __syncthreads();
    }
    acc += bias[tid];
    if (tid >= C) {
        float x = acc;
        s_std[tid - C] = fmaxf(x, 0.f) + log1pf(expf(-fabsf(x))) + 1e-10f;
    }
    __syncthreads();
    float kl = 0.f;
    if (tid < C) {
        float mu = acc, sd = s_std[tid];
        kl = -logf(sd) + 0.5f * fmaf(sd, sd, mu * mu) - 0.5f;
        mu_out[(size_t)n * C + tid] = mu;
    }
    float tot = blockReduceSum(kl, s_red);
    if (tid == 0) atomicAdd(acc_slot, (double)tot);
}

// ---------------- temporal fusion / activations ----------------
__global__ void fuse1_kernel() {
    int i = blockIdx.x * blockDim.x + threadIdx.x;
    if (i < NN * 128) {
        float m0 = g_mu0[i], m1 = g_mu1[i];
        g_mu1[i] = fmaxf(0.4f * m0 + 0.2f * m1, 0.f);
        g_mu0[i] = fmaxf(m0, 0.f);
    }
}

__global__ void fuse2_kernel(float* __restrict__ out) {
    int i = blockIdx.x * blockDim.x + threadIdx.x;
    if (i < NN * 64) out[NN * 64 + i] = 0.4f * out[i] + 0.2f * g_mu1[i];
}

__global__ void finalize_kernel(float* __restrict__ out, int out_size) {
    double ixz = (g_acc[0] + g_acc[1] + g_acc[2] + g_acc[3]) / (4.0 * (double)NN);
    double skl = (g_acc[4] + g_acc[5] + g_acc[6] + g_acc[7]) / (4.0 * (double)EE);
    out[out_size - 2] = (float)ixz;
    out[out_size - 1] = (float)skl;
}

// ---------------- launch ----------------
extern "C" void kernel_launch(void* const* d_in, const int* in_sizes, int n_in,
                              void* d_out, int out_size) {
    const float* x_all = (const float*)d_in[0];   // [T, N, 128]
    const int* ei = (const int*)d_in[1];          // [T, 2, E]
    const float* W1 = (const float*)d_in[2];      // [128, 256]
    const float* att1 = (const float*)d_in[3];    // [512]
    const float* b1 = (const float*)d_in[4];      // [256]
    const float* W2 = (const float*)d_in[5];      // [128, 128]
    const float* att2 = (const float*)d_in[6];    // [256]
    const float* b2 = (const float*)d_in[7];      // [128]
    float* out = (float*)d_out;

    float *p_h, *p_mu0, *p_mu1, *p_alpha;
    int *p_csrc, *p_rowptr;
    double* p_acc;
    cudaGetSymbolAddress((void**)&p_h, g_h);
    cudaGetSymbolAddress((void**)&p_mu0, g_mu0);
    cudaGetSymbolAddress((void**)&p_mu1, g_mu1);
    cudaGetSymbolAddress((void**)&p_alpha, g_alpha);
    cudaGetSymbolAddress((void**)&p_csrc, g_csrc);
    cudaGetSymbolAddress((void**)&p_rowptr, g_rowptr);
    cudaGetSymbolAddress((void**)&p_acc, g_acc);

    const int EB = (EE + 255) / 256;
    const int SB = (NN * 32 + 255) / 256;
    const int MB = (NN + 127) / 128;  // 235
    const int* src0 = ei;
    const int* dst0 = ei + EE;
    const int* src1 = ei + (size_t)2 * EE;
    const int* dst1 = ei + (size_t)3 * EE;

    // GEMM at launch index 3 (where ncu's bounded capture lands).
    zero_kernel<<<(TT * NN + 255) / 256, 256>>>();                      // 0
    hist_kernel<<<EB, 256>>>(dst0, 0);                                  // 1
    scan_kernel<<<1, 1024>>>(0);                                        // 2
    gemm_tc_kernel<<<dim3(4, MB), 256>>>(x_all, W1, p_h, NN, 256);      // 3
    scatter_kernel<<<EB, 256>>>(src0, dst0, 0);                         // 4
    hist_kernel<<<EB, 256>>>(dst1, 1);                                  // 5
    scan_kernel<<<1, 1024>>>(1);                                        // 6
    scatter_kernel<<<EB, 256>>>(src1, dst1, 1);                         // 7
    watt_kernel<<<1, 128>>>(W1, att1, 256);                             // 8

    // -------- layer 1 (C = 128), t = 0 (GEMM already done) --------
    scores_x_kernel<<<SB, 256>>>((const float4*)x_all);
    alpha_kernel<<<EB, 256>>>(0, p_acc + 4);
    agg_kernel<128><<<NN, 256>>>(p_h, p_alpha, p_csrc, p_rowptr, b1, p_mu0, p_acc + 0);
    // -------- layer 1, t = 1 --------
    gemm_tc_kernel<<<dim3(4, MB), 256>>>(x_all + (size_t)NN * KDIM, W1, p_h, NN, 256);
    scores_x_kernel<<<SB, 256>>>((const float4*)(x_all + (size_t)NN * KDIM));
    alpha_kernel<<<EB, 256>>>(1, p_acc + 5);
    agg_kernel<128><<<NN, 256>>>(p_h, p_alpha, p_csrc + EE, p_rowptr + (NN + 1), b1,
                                 p_mu1, p_acc + 1);
    fuse1_kernel<<<(NN * 128 + 255) / 256, 256>>>();

    // -------- layer 2 (C = 64) --------
    watt_kernel<<<1, 128>>>(W2, att2, 128);
    for (int t = 0; t < TT; t++) {
        const float* xin = t ? p_mu1 : p_mu0;
        gemm_tc_kernel<<<dim3(2, MB), 256>>>(xin, W2, p_h, NN, 128);
        scores_x_kernel<<<SB, 256>>>((const float4*)xin);
        alpha_kernel<<<EB, 256>>>(t, p_acc + 6 + t);
        agg_kernel<64><<<NN, 128>>>(p_h, p_alpha, p_csrc + (size_t)t * EE,
                                    p_rowptr + (size_t)t * (NN + 1), b2,
                                    t ? p_mu1 : out, p_acc + 2 + t);
    }
    fuse2_kernel<<<(NN * 64 + 255) / 256, 256>>>(out);
    finalize_kernel<<<1, 1>>>(out, out_size);
}

// round 11
// speedup vs baseline: 1.8579x; 1.1869x over previous
#include <cuda_runtime.h>
#include <math.h>
#include <stdint.h>

#define NN 30000
#define EE 510000      // 30000*16 + 30000 self loops
#define TT 2
#define KDIM 128       // F_IN == H1 == 128 (GEMM K for both layers)

// ---------------- scratch (device globals; no allocation allowed) ----------------
__device__ float  g_h[(size_t)NN * 256];     // GEMM output t0
__device__ float  g_h2[(size_t)NN * 256];    // GEMM output t1
__device__ float  g_mu0[(size_t)NN * 128];
__device__ float  g_mu1[(size_t)NN * 128];
__device__ float  g_alpha[TT][EE];
__device__ float  g_si[TT][NN];
__device__ float  g_sj[TT][NN];
__device__ float  g_watt[2][128];            // W @ att halves (current layer)
__device__ float  g_invdeg[TT][NN];
__device__ int    g_deg[TT][NN];
__device__ int    g_rowptr[TT][NN + 1];
__device__ int    g_woff[TT][NN];
__device__ int    g_csrc[TT][EE];
__device__ int    g_cdst[TT][EE];
__device__ double g_acc[8];  // [0..3] ixz sums, [4..7] skl sums

// ---------------- helpers ----------------
__device__ __forceinline__ float blockReduceSum(float v, float* sm) {
    int lane = threadIdx.x & 31, wid = threadIdx.x >> 5;
#pragma unroll
    for (int o = 16; o; o >>= 1) v += __shfl_down_sync(0xffffffffu, v, o);
    if (lane == 0) sm[wid] = v;
    __syncthreads();
    int nw = (blockDim.x + 31) >> 5;
    v = (threadIdx.x < nw) ? sm[threadIdx.x] : 0.f;
    if (wid == 0) {
#pragma unroll
        for (int o = 16; o; o >>= 1) v += __shfl_down_sync(0xffffffffu, v, o);
    }
    return v;  // valid on thread 0
}

__device__ __forceinline__ uint32_t f2tf32(float f) {
    uint32_t u;
    asm("cvt.rna.tf32.f32 %0, %1;" : "=r"(u) : "f"(f));
    return u;
}

// ---------------- setup kernels ----------------
__global__ void zero_kernel() {
    int i = blockIdx.x * blockDim.x + threadIdx.x;
    if (i < TT * NN) (&g_deg[0][0])[i] = 0;
    if (i < 8) g_acc[i] = 0.0;
}

__global__ void hist_kernel(const int* __restrict__ ei) {
    int t = blockIdx.y;
    int e = blockIdx.x * blockDim.x + threadIdx.x;
    const int* dst = ei + (size_t)t * 2 * EE + EE;
    if (e < EE) atomicAdd(&g_deg[t][dst[e]], 1);
}

__global__ void scan_kernel() {
    int t = blockIdx.x;
    const int T = 1024;
    int tid = threadIdx.x;
    const int chunk = (NN + T - 1) / T;  // 30
    int s0 = tid * chunk;
    int sum = 0;
    for (int i = 0; i < chunk; i++) {
        int idx = s0 + i;
        if (idx < NN) sum += g_deg[t][idx];
    }
    int lane = tid & 31, wid = tid >> 5;
    int v = sum;
#pragma unroll
    for (int o = 1; o < 32; o <<= 1) {
        int u = __shfl_up_sync(0xffffffffu, v, o);
        if (lane >= o) v += u;
    }
    __shared__ int ws[32];
    if (lane == 31) ws[wid] = v;
    __syncthreads();
    if (wid == 0) {
        int w = ws[lane];
#pragma unroll
        for (int o = 1; o < 32; o <<= 1) {
            int u = __shfl_up_sync(0xffffffffu, w, o);
            if (lane >= o) w += u;
        }
        ws[lane] = w;
    }
    __syncthreads();
    int excl = (v - sum) + (wid > 0 ? ws[wid - 1] : 0);
    int run = excl;
    for (int i = 0; i < chunk; i++) {
        int idx = s0 + i;
        if (idx < NN) {
            int d = g_deg[t][idx];
            g_rowptr[t][idx] = run;
            g_woff[t][idx] = run;
            g_invdeg[t][idx] = 1.0f / (float)d;
            run += d;
        }
    }
    if (tid == T - 1) g_rowptr[t][NN] = run;
}

__global__ void scatter_kernel(const int* __restrict__ ei) {
    int t = blockIdx.y;
    int e = blockIdx.x * blockDim.x + threadIdx.x;
    const int* src = ei + (size_t)t * 2 * EE;
    const int* dst = src + EE;
    if (e < EE) {
        int d = dst[e];
        int pos = atomicAdd(&g_woff[t][d], 1);
        g_csrc[t][pos] = src[e];
        g_cdst[t][pos] = d;
    }
}

// ---------------- TF32 tensor-core GEMM (pipelined) ------------------------------
// C[M,Ncols] = A[M,128] * B[128,Ncols].  Tile 128x64, 256 threads, 8 warps of 32x32.
// B tile [128][64] loaded ONCE (full K) transposed+tf32 into smem.
// A tile double-buffered via cp.async (raw fp32), tf32 cvt in registers.
// blockIdx.z selects (A0,C0) vs (A1,C1) — the two snapshots.
#define ASTR 36
#define BSTR 132
#define A_STAGE (128 * ASTR)
#define GEMM_SMEM ((2 * A_STAGE + 64 * BSTR) * 4)
__global__ void __launch_bounds__(256)
gemm_tc_kernel(const float* __restrict__ A0, const float* __restrict__ A1,
               const float* __restrict__ B, float* __restrict__ C0,
               float* __restrict__ C1, int M, int Ncols) {
    extern __shared__ float smem[];
    float* Bs = smem + 2 * A_STAGE;
    const float* A = blockIdx.z ? A1 : A0;
    float* C = blockIdx.z ? C1 : C0;
    int tid = threadIdx.x, lane = tid & 31, wid = tid >> 5;
    int warp_m = wid & 3, warp_n = wid >> 2;
    int row0 = blockIdx.y * 128, col0 = blockIdx.x * 64;
    int sub = lane >> 3, l8 = lane & 7;
    uint32_t as_base = (uint32_t)__cvta_generic_to_shared(smem);
    uint32_t bs_base = as_base + 2 * A_STAGE * 4;

    // B fill: full K, transposed, tf32-converted (one time)
    for (int i = tid; i < 128 * 64; i += 256) {
        int k = i >> 6, n = i & 63;
        Bs[n * BSTR + k] = __uint_as_float(f2tf32(B[(size_t)k * Ncols + col0 + n]));
    }

    // A stage fill via cp.async (4 x 16B per thread); OOB rows: clamped src + zfill
#define FILL_A(buf, k0)                                                              \
    {                                                                                \
        _Pragma("unroll") for (int i = 0; i < 4; i++) {                              \
            int idx = tid + i * 256;                                                 \
            int r = idx >> 3, kc = (idx & 7) * 4;                                    \
            uint32_t dstp = as_base + (uint32_t)(((buf) * A_STAGE + r * ASTR + kc) * 4); \
            int rr = row0 + r;                                                       \
            int ok = rr < M;                                                         \
            int rs = ok ? rr : (M - 1);                                              \
            const float* srcp = A + (size_t)rs * KDIM + (k0) + kc;                   \
            int sz = ok ? 16 : 0;                                                    \
            asm volatile("cp.async.ca.shared.global [%0], [%1], 16, %2;"             \
                         :: "r"(dstp), "l"(srcp), "r"(sz));                          \
        }                                                                            \
    }

    FILL_A(0, 0);
    asm volatile("cp.async.commit_group;");

    float acc[2][4][4] = {};
    int a_r = warp_m * 32 + (sub & 1) * 8 + l8;
    int a_c = (sub >> 1) * 4;
    int b_r = warp_n * 32 + (sub >> 1) * 8 + l8;
    int b_c = (sub & 1) * 4;

    int s = 0;
    for (int k0 = 0; k0 < KDIM; k0 += 32, s ^= 1) {
        if (k0 + 32 < KDIM) {
            FILL_A(s ^ 1, k0 + 32);
            asm volatile("cp.async.commit_group;");
            asm volatile("cp.async.wait_group 1;");
        } else {
            asm volatile("cp.async.wait_group 0;");
        }
        __syncthreads();
        int abase = s * A_STAGE;
#pragma unroll
        for (int kk = 0; kk < 32; kk += 8) {
            uint32_t a[2][4], b[2][4];
#pragma unroll
            for (int im = 0; im < 2; im++) {
                uint32_t addr = as_base + (uint32_t)((abase + (a_r + im * 16) * ASTR + a_c + kk) * 4);
                asm volatile("ldmatrix.sync.aligned.m8n8.x4.shared.b16 {%0,%1,%2,%3}, [%4];"
                             : "=r"(a[im][0]), "=r"(a[im][1]), "=r"(a[im][2]), "=r"(a[im][3])
                             : "r"(addr));
            }
#pragma unroll
            for (int im = 0; im < 2; im++)
#pragma unroll
                for (int j = 0; j < 4; j++)
                    a[im][j] = f2tf32(__uint_as_float(a[im][j]));
#pragma unroll
            for (int p = 0; p < 2; p++) {
                uint32_t addr = bs_base + (uint32_t)(((b_r + p * 16) * BSTR + b_c + k0 + kk) * 4);
                asm volatile("ldmatrix.sync.aligned.m8n8.x4.shared.b16 {%0,%1,%2,%3}, [%4];"
                             : "=r"(b[p][0]), "=r"(b[p][1]), "=r"(b[p][2]), "=r"(b[p][3])
                             : "r"(addr));
            }
#pragma unroll
            for (int im = 0; im < 2; im++)
#pragma unroll
                for (int in = 0; in < 4; in++) {
                    uint32_t b0 = b[in >> 1][(in & 1) * 2 + 0];
                    uint32_t b1 = b[in >> 1][(in & 1) * 2 + 1];
                    asm volatile(
                        "mma.sync.aligned.m16n8k8.row.col.f32.tf32.tf32.f32 "
                        "{%0,%1,%2,%3}, {%4,%5,%6,%7}, {%8,%9}, {%0,%1,%2,%3};"
                        : "+f"(acc[im][in][0]), "+f"(acc[im][in][1]),
                          "+f"(acc[im][in][2]), "+f"(acc[im][in][3])
                        : "r"(a[im][0]), "r"(a[im][1]), "r"(a[im][2]), "r"(a[im][3]),
                          "r"(b0), "r"(b1));
                }
        }
        __syncthreads();
    }
#pragma unroll
    for (int im = 0; im < 2; im++) {
        int r = row0 + warp_m * 32 + im * 16 + (lane >> 2);
#pragma unroll
        for (int in = 0; in < 4; in++) {
            int c = col0 + warp_n * 32 + in * 8 + (lane & 3) * 2;
            if (r < M)
                *(float2*)&C[(size_t)r * Ncols + c] = make_float2(acc[im][in][0], acc[im][in][1]);
            if (r + 8 < M)
                *(float2*)&C[(size_t)(r + 8) * Ncols + c] = make_float2(acc[im][in][2], acc[im][in][3]);
        }
    }
}

// ---------------- W @ att precompute ----------------
__global__ void watt_kernel(const float* __restrict__ W, const float* __restrict__ att, int TC) {
    int k = threadIdx.x;  // 0..127
    const float* row = W + (size_t)k * TC;
    float a = 0.f, b = 0.f;
    for (int c = 0; c < TC; c++) {
        float v = row[c];
        a = fmaf(v, att[c], a);
        b = fmaf(v, att[TC + c], b);
    }
    g_watt[0][k] = a;
    g_watt[1][k] = b;
}

// ---------------- per-node attention scores (both snapshots) ----------------
__global__ void scores_x_kernel(const float4* __restrict__ x0, const float4* __restrict__ x1) {
    int t = blockIdx.y;
    const float4* x4 = t ? x1 : x0;
    int gw = (blockIdx.x * blockDim.x + threadIdx.x) >> 5;
    int lane = threadIdx.x & 31;
    if (gw >= NN) return;
    float4 v = x4[(size_t)gw * 32 + lane];
    const float4 wa = *(const float4*)&g_watt[0][lane * 4];
    const float4 wb = *(const float4*)&g_watt[1][lane * 4];
    float a = v.x * wa.x + v.y * wa.y + v.z * wa.z + v.w * wa.w;
    float b = v.x * wb.x + v.y * wb.y + v.z * wb.z + v.w * wb.w;
#pragma unroll
    for (int o = 16; o; o >>= 1) {
        a += __shfl_down_sync(0xffffffffu, a, o);
        b += __shfl_down_sync(0xffffffffu, b, o);
    }
    if (lane == 0) {
        g_si[t][gw] = a;
        g_sj[t][gw] = b;
    }
}

// ---------------- per-edge alpha + skl (both snapshots) ----------------
__global__ void alpha_kernel(double* __restrict__ skl_base) {
    __shared__ float s_red[32];
    int t = blockIdx.y;
    int e = blockIdx.x * blockDim.x + threadIdx.x;
    float skl = 0.f;
    if (e < EE) {
        int d = g_cdst[t][e], s = g_csrc[t][e];
        float l = g_si[t][d] + g_sj[t][s];
        l = l > 0.f ? l : 0.2f * l;
        float p = 1.f / (1.f + expf(-l));
        p = fminf(fmaxf(p, 0.01f), 0.99f);
        g_alpha[t][e] = p * g_invdeg[t][d];
        float q = 1.0f / (1.0f + expf(-(1.0f / 15.0f)));
        skl = p * (logf(p) - logf(q)) + (1.f - p) * (logf(1.f - p) - logf(1.f - q));
    }
    float tot = blockReduceSum(skl, s_red);
    if (threadIdx.x == 0) atomicAdd(skl_base + t, (double)tot);
}

// ---------------- aggregation + KL epilogue (both snapshots) ----------------
template <int C>
__global__ void agg_kernel(const float* __restrict__ h0, const float* __restrict__ h1,
                           const float* __restrict__ bias, float* __restrict__ out0,
                           float* __restrict__ out1, double* __restrict__ ixz_base) {
    constexpr int TC = 2 * C;
    __shared__ float s_alpha[TC];
    __shared__ int s_src[TC];
    __shared__ float s_std[C];
    __shared__ float s_red[32];
    int n = blockIdx.x, t = blockIdx.y, tid = threadIdx.x;
    const float* h = t ? h1 : h0;
    const float* alpha = g_alpha[t];
    const int* csrc = g_csrc[t];
    float* mu_out = t ? out1 : out0;
    int start = g_rowptr[t][n], end = g_rowptr[t][n + 1];
    float acc = 0.f;
    for (int base = start; base < end; base += TC) {
        int cnt = min(TC, end - base);
        if (tid < cnt) {
            s_alpha[tid] = alpha[base + tid];
            s_src[tid] = csrc[base + tid];
        }
        __syncthreads();
        for (int i = 0; i < cnt; i++)
            acc = fmaf(s_alpha[i], h[(size_t)s_src[i] * TC + tid], acc);
        __syncthreads();
    }
    acc += bias[tid];
    if (tid >= C) {
        float x = acc;
        s_std[tid - C] = fmaxf(x, 0.f) + log1pf(expf(-fabsf(x))) + 1e-10f;
    }
    __syncthreads();
    float kl = 0.f;
    if (tid < C) {
        float mu = acc, sd = s_std[tid];
        kl = -logf(sd) + 0.5f * fmaf(sd, sd, mu * mu) - 0.5f;
        mu_out[(size_t)n * C + tid] = mu;
    }
    float tot = blockReduceSum(kl, s_red);
    if (tid == 0) atomicAdd(ixz_base + t, (double)tot);
}

// ---------------- temporal fusion / activations ----------------
__global__ void fuse1_kernel() {
    int i = blockIdx.x * blockDim.x + threadIdx.x;
    if (i < NN * 128) {
        float m0 = g_mu0[i], m1 = g_mu1[i];
        g_mu1[i] = fmaxf(0.4f * m0 + 0.2f * m1, 0.f);
        g_mu0[i] = fmaxf(m0, 0.f);
    }
}

__global__ void fuse2_kernel(float* __restrict__ out) {
    int i = blockIdx.x * blockDim.x + threadIdx.x;
    if (i < NN * 64) out[NN * 64 + i] = 0.4f * out[i] + 0.2f * g_mu1[i];
}

__global__ void finalize_kernel(float* __restrict__ out, int out_size) {
    double ixz = (g_acc[0] + g_acc[1] + g_acc[2] + g_acc[3]) / (4.0 * (double)NN);
    double skl = (g_acc[4] + g_acc[5] + g_acc[6] + g_acc[7]) / (4.0 * (double)EE);
    out[out_size - 2] = (float)ixz;
    out[out_size - 1] = (float)skl;
}

// ---------------- launch ----------------
extern "C" void kernel_launch(void* const* d_in, const int* in_sizes, int n_in,
                              void* d_out, int out_size) {
    const float* x_all = (const float*)d_in[0];   // [T, N, 128]
    const int* ei = (const int*)d_in[1];          // [T, 2, E]
    const float* W1 = (const float*)d_in[2];      // [128, 256]
    const float* att1 = (const float*)d_in[3];    // [512]
    const float* b1 = (const float*)d_in[4];      // [256]
    const float* W2 = (const float*)d_in[5];      // [128, 128]
    const float* att2 = (const float*)d_in[6];    // [256]
    const float* b2 = (const float*)d_in[7];      // [128]
    float* out = (float*)d_out;

    // Opt-in smem (idempotent; done before any launch, error ignored deterministically)
    (void)cudaFuncSetAttribute(gemm_tc_kernel,
                               cudaFuncAttributeMaxDynamicSharedMemorySize, GEMM_SMEM);

    float *p_h, *p_h2, *p_mu0, *p_mu1;
    double* p_acc;
    cudaGetSymbolAddress((void**)&p_h, g_h);
    cudaGetSymbolAddress((void**)&p_h2, g_h2);
    cudaGetSymbolAddress((void**)&p_mu0, g_mu0);
    cudaGetSymbolAddress((void**)&p_mu1, g_mu1);
    cudaGetSymbolAddress((void**)&p_acc, g_acc);

    const int EB = (EE + 255) / 256;
    const int SB = (NN * 32 + 255) / 256;
    const int MB = (NN + 127) / 128;  // 235

    zero_kernel<<<(TT * NN + 255) / 256, 256>>>();                        // 0
    hist_kernel<<<dim3(EB, 2), 256>>>(ei);                                // 1
    scan_kernel<<<2, 1024>>>();                                           // 2
    gemm_tc_kernel<<<dim3(4, MB, 2), 256, GEMM_SMEM>>>(                   // 3 <- profiled
        x_all, x_all + (size_t)NN * KDIM, W1, p_h, p_h2, NN, 256);
    scatter_kernel<<<dim3(EB, 2), 256>>>(ei);                             // 4
    watt_kernel<<<1, 128>>>(W1, att1, 256);                               // 5
    scores_x_kernel<<<dim3(SB, 2), 256>>>(                                // 6
        (const float4*)x_all, (const float4*)(x_all + (size_t)NN * KDIM));
    alpha_kernel<<<dim3(EB, 2), 256>>>(p_acc + 4);                        // 7
    agg_kernel<128><<<dim3(NN, 2), 256>>>(p_h, p_h2, b1, p_mu0, p_mu1, p_acc + 0);  // 8
    fuse1_kernel<<<(NN * 128 + 255) / 256, 256>>>();                      // 9

    watt_kernel<<<1, 128>>>(W2, att2, 128);                               // 10
    gemm_tc_kernel<<<dim3(2, MB, 2), 256, GEMM_SMEM>>>(                   // 11
        p_mu0, p_mu1, W2, p_h, p_h2, NN, 128);
    scores_x_kernel<<<dim3(SB, 2), 256>>>((const float4*)p_mu0, (const float4*)p_mu1);  // 12
    alpha_kernel<<<dim3(EB, 2), 256>>>(p_acc + 6);                        // 13
    agg_kernel<64><<<dim3(NN, 2), 128>>>(p_h, p_h2, b2, out, p_mu1, p_acc + 2);  // 14
    fuse2_kernel<<<(NN * 64 + 255) / 256, 256>>>(out);                    // 15
    finalize_kernel<<<1, 1>>>(out, out_size);                             // 16
}